// round 6
// baseline (speedup 1.0000x reference)
#include <cuda_runtime.h>
#include <cuda_bf16.h>
#include <cstdint>

// Problem dims (fixed)
constexpr int Bn = 2;
constexpr int Sn = 2048;
constexpr int Dn = 1024;
constexpr int Hn = 16;
constexpr int An = 64;
constexpr int Mrows = Bn * Sn;        // 4096
constexpr int HA = Hn * An;           // 1024

// Scratch (device globals; allocation-free). All tf32-valued fp32 bits.
__device__ __align__(256) float g_q[(size_t)Bn * Hn * Sn * An];   // [B,H,S,A] (tf32)
__device__ __align__(256) float g_k[(size_t)Bn * Hn * Sn * An];   // (tf32)
__device__ __align__(256) float g_v[(size_t)Bn * Hn * Sn * An];   // (tf32)
__device__ __align__(256) float g_z[(size_t)Bn * Sn * Hn * An];   // [B,S,H,A] (tf32)
__device__ __align__(256) float g_at[(size_t)Mrows * Dn];         // residual (tf32)
__device__ __align__(256) float g_w4[(size_t)4 * 1024 * 1024];    // Wq,Wk,Wv,Wo (tf32)

// ---------------------------------------------------------------------------
// Helpers (sm_80-baseline PTX: cp.async + mma.sync tf32; NO tcgen05)
// ---------------------------------------------------------------------------
__device__ __forceinline__ void cp_async16(uint32_t dst, const void* src) {
    asm volatile("cp.async.cg.shared.global [%0], [%1], 16;" :: "r"(dst), "l"(src) : "memory");
}
__device__ __forceinline__ uint32_t smem_u32(const void* p) {
    uint32_t a;
    asm("{ .reg .u64 t; cvta.to.shared.u64 t, %1; cvt.u32.u64 %0, t; }" : "=r"(a) : "l"(p));
    return a;
}
__device__ __forceinline__ void cp_commit() {
    asm volatile("cp.async.commit_group;" ::: "memory");
}
template <int N>
__device__ __forceinline__ void cp_wait() {
    asm volatile("cp.async.wait_group %0;" :: "n"(N) : "memory");
}
__device__ __forceinline__ uint32_t f2tf32(float x) {
    uint32_t r;
    asm("cvt.rna.tf32.f32 %0, %1;" : "=r"(r) : "f"(x));
    return r;
}
__device__ __forceinline__ float f2tf32f(float x) {
    return __uint_as_float(f2tf32(x));
}
__device__ __forceinline__ void mma_tf32_16n8k8(float* c, const uint32_t* a, const uint32_t* b) {
    asm volatile(
        "mma.sync.aligned.m16n8k8.row.col.f32.tf32.tf32.f32 "
        "{%0,%1,%2,%3}, {%4,%5,%6,%7}, {%8,%9}, {%0,%1,%2,%3};"
        : "+f"(c[0]), "+f"(c[1]), "+f"(c[2]), "+f"(c[3])
        : "r"(a[0]), "r"(a[1]), "r"(a[2]), "r"(a[3]), "r"(b[0]), "r"(b[1]));
}

// ---------------------------------------------------------------------------
// Pre-pass: convert fp32 -> tf32-valued fp32 into device globals.
// sel: 0 residual->g_at ; 1..3 Wq/Wk/Wv -> g_w4[sel-1] ; 4 Wo -> g_w4[3]
// ---------------------------------------------------------------------------
__global__ __launch_bounds__(256) void tf32_convert_kernel(const float* __restrict__ src,
                                                           int sel, int n4)
{
    float* dst;
    if (sel == 0) dst = g_at;
    else          dst = g_w4 + (size_t)(sel - 1) * (1024 * 1024);
    int idx = blockIdx.x * 256 + threadIdx.x;
    int stride = gridDim.x * 256;
    for (int i = idx; i < n4; i += stride) {
        float4 v = ((const float4*)src)[i];
        v.x = f2tf32f(v.x);
        v.y = f2tf32f(v.y);
        v.z = f2tf32f(v.z);
        v.w = f2tf32f(v.w);
        ((float4*)dst)[i] = v;
    }
}

// ---------------------------------------------------------------------------
// tf32 mma.sync GEMM: inputs pre-converted to tf32; NO cvt in the hot loop.
// MODE 0: QKV from g_at x g_w4[z] -> g_q/g_k/g_v (tf32-rounded stores)
// MODE 1: out  from g_z  x g_w4[3] -> outp (full fp32)
// BM=128, BN=128, BK=32, 256 threads (8 warps: 2 m x 4 n), warp tile 64x32.
// ---------------------------------------------------------------------------
constexpr int LDA = 36;
constexpr int LDB = 136;
constexpr int A_STG = 128 * LDA;
constexpr int B_STG = 32 * LDB;
constexpr int STG_FLOATS = A_STG + B_STG;
constexpr int NSTAGE = 3;
constexpr int GEMM_SMEM = NSTAGE * STG_FLOATS * 4;
constexpr int KCHUNKS = 1024 / 32;

template<int MODE>
__global__ __launch_bounds__(256) void gemm_mma_kernel(
    const float* __restrict__ b0, const float* __restrict__ b1, const float* __restrict__ b2,
    float* __restrict__ outp)
{
    extern __shared__ __align__(16) uint32_t smem[];

    const int tid = threadIdx.x;
    const int lane = tid & 31;
    const int wid = tid >> 5;
    const int warp_m = wid & 1;
    const int warp_n = wid >> 1;
    const int grp = lane >> 2;
    const int qd = lane & 3;

    const int m0 = blockIdx.y * 128;
    const int n0 = blockIdx.x * 128;
    const int z = blockIdx.z;

    const float* A = (MODE == 0) ? (const float*)g_at : (const float*)g_z;
    const float* W = (MODE == 0) ? (g_w4 + (size_t)z * (1024 * 1024))
                                 : (g_w4 + (size_t)3 * (1024 * 1024));
    const float* bias = (MODE == 0) ? ((z == 0) ? b0 : (z == 1) ? b1 : b2) : b0;

    const uint32_t smem_base = smem_u32(smem);

    auto produce = [&](int kc) {
        const int slot = kc % NSTAGE;
        const uint32_t sA = smem_base + (uint32_t)(slot * STG_FLOATS) * 4;
        const uint32_t sB = sA + (uint32_t)A_STG * 4;
        #pragma unroll
        for (int i = 0; i < 4; ++i) {
            int task = i * 256 + tid;
            int r = task >> 3;
            int sgm = task & 7;
            cp_async16(sA + (uint32_t)(r * LDA + sgm * 4) * 4,
                       A + (size_t)(m0 + r) * 1024 + kc * 32 + sgm * 4);
        }
        #pragma unroll
        for (int i = 0; i < 4; ++i) {
            int task = i * 256 + tid;
            int kr = task >> 5;
            int sgm = task & 31;
            int nl = sgm * 4;
            const float* src;
            if (MODE == 0) {
                int ng = n0 + nl;
                src = W + (size_t)(ng >> 6) * (Dn * An) + (size_t)(kc * 32 + kr) * An + (ng & 63);
            } else {
                src = W + (size_t)(kc * 32 + kr) * Dn + n0 + nl;
            }
            cp_async16(sB + (uint32_t)(kr * LDB + nl) * 4, src);
        }
        cp_commit();
    };

    float acc[4][4][4];
    #pragma unroll
    for (int mt = 0; mt < 4; ++mt)
        #pragma unroll
        for (int nt = 0; nt < 4; ++nt)
            #pragma unroll
            for (int e = 0; e < 4; ++e) acc[mt][nt][e] = 0.0f;

    produce(0);
    produce(1);

    for (int kc = 0; kc < KCHUNKS; ++kc) {
        cp_wait<1>();
        __syncthreads();
        if (kc + 2 < KCHUNKS) produce(kc + 2);

        const int slot = kc % NSTAGE;
        const uint32_t* sA = smem + slot * STG_FLOATS;
        const uint32_t* sB = sA + A_STG;

        #pragma unroll
        for (int ks = 0; ks < 4; ++ks) {
            uint32_t af[4][4], bf[4][2];
            #pragma unroll
            for (int mt = 0; mt < 4; ++mt) {
                const int rb = warp_m * 64 + mt * 16 + grp;
                const int cb = ks * 8 + qd;
                af[mt][0] = sA[rb * LDA + cb];
                af[mt][1] = sA[(rb + 8) * LDA + cb];
                af[mt][2] = sA[rb * LDA + cb + 4];
                af[mt][3] = sA[(rb + 8) * LDA + cb + 4];
            }
            #pragma unroll
            for (int nt = 0; nt < 4; ++nt) {
                const int nb = warp_n * 32 + nt * 8 + grp;
                bf[nt][0] = sB[(ks * 8 + qd) * LDB + nb];
                bf[nt][1] = sB[(ks * 8 + qd + 4) * LDB + nb];
            }
            #pragma unroll
            for (int mt = 0; mt < 4; ++mt)
                #pragma unroll
                for (int nt = 0; nt < 4; ++nt)
                    mma_tf32_16n8k8(acc[mt][nt], af[mt], bf[nt]);
        }
        __syncthreads();
    }

    #pragma unroll
    for (int mt = 0; mt < 4; ++mt) {
        #pragma unroll
        for (int half = 0; half < 2; ++half) {
            const int m = m0 + warp_m * 64 + mt * 16 + grp + half * 8;
            #pragma unroll
            for (int nt = 0; nt < 4; ++nt) {
                const int n = n0 + warp_n * 32 + nt * 8 + qd * 2;
                float2 v;
                v.x = acc[mt][nt][half * 2 + 0] + bias[n];
                v.y = acc[mt][nt][half * 2 + 1] + bias[n + 1];
                if (MODE == 0) {
                    // store tf32-rounded: downstream MMAs consume without cvt
                    v.x = f2tf32f(v.x);
                    v.y = f2tf32f(v.y);
                    const int b = m >> 11;
                    const int s = m & 2047;
                    float* O = (z == 0) ? g_q : (z == 1) ? g_k : g_v;
                    *(float2*)&O[(((size_t)b * Hn + (n >> 6)) * Sn + s) * An + (n & 63)] = v;
                } else {
                    *(float2*)&outp[(size_t)m * Dn + n] = v;   // final: full fp32
                }
            }
        }
    }
}

// ---------------------------------------------------------------------------
// Causal flash attention (mma.sync tf32). Inputs g_q/g_k/g_v are tf32-valued:
// SMEM fills are plain bit-copies (Q scale 0.125 is exact). P still cvt'd.
// ---------------------------------------------------------------------------
constexpr int LDQ = 68;
constexpr int LDK = 68;
constexpr int LDV = 72;
constexpr int LDP = 68;
constexpr int FL_SQ = 128 * LDQ;
constexpr int FL_SK = 64 * LDK;
constexpr int FL_SV = 64 * LDV;
constexpr int FL_SP = 128 * LDP;
constexpr int FLASH_SMEM_BYTES = (FL_SQ + FL_SK + FL_SV + FL_SP) * 4;

__global__ __launch_bounds__(256) void flash_mma_kernel()
{
    extern __shared__ uint32_t sm_u[];
    uint32_t* sQ = sm_u;
    uint32_t* sK = sQ + FL_SQ;
    uint32_t* sV = sK + FL_SK;
    uint32_t* sP = sV + FL_SV;

    const int tid = threadIdx.x;
    const int lane = tid & 31;
    const int wid = tid >> 5;
    const int grp = lane >> 2;
    const int qd = lane & 3;

    const int bh = blockIdx.y;
    const size_t base = (size_t)bh * Sn * An;
    const int q0 = blockIdx.x * 128;

    // Q fill: values already tf32; *0.125 exact (power of two)
    for (int idx = tid; idx < 128 * 16; idx += 256) {
        int r = idx >> 4;
        int c4 = (idx & 15) * 4;
        float4 v = *(const float4*)&g_q[base + (size_t)(q0 + r) * An + c4];
        sQ[r * LDQ + c4 + 0] = __float_as_uint(v.x * 0.125f);
        sQ[r * LDQ + c4 + 1] = __float_as_uint(v.y * 0.125f);
        sQ[r * LDQ + c4 + 2] = __float_as_uint(v.z * 0.125f);
        sQ[r * LDQ + c4 + 3] = __float_as_uint(v.w * 0.125f);
    }
    __syncthreads();

    const int r0 = wid * 16 + grp;
    uint32_t qf[8][4];
    #pragma unroll
    for (int ks = 0; ks < 8; ++ks) {
        qf[ks][0] = sQ[r0 * LDQ + ks * 8 + qd];
        qf[ks][1] = sQ[(r0 + 8) * LDQ + ks * 8 + qd];
        qf[ks][2] = sQ[r0 * LDQ + ks * 8 + qd + 4];
        qf[ks][3] = sQ[(r0 + 8) * LDQ + ks * 8 + qd + 4];
    }

    float m0r = -1e30f, m1r = -1e30f, l0r = 0.0f, l1r = 0.0f;
    float o[8][4];
    #pragma unroll
    for (int nt = 0; nt < 8; ++nt)
        #pragma unroll
        for (int e = 0; e < 4; ++e) o[nt][e] = 0.0f;

    const int grow0 = q0 + r0;
    const int grow1 = grow0 + 8;

    for (int j0 = 0; j0 < q0 + 128; j0 += 64) {
        // K/V fill: plain bit copies (already tf32)
        for (int idx = tid; idx < 64 * 16; idx += 256) {
            int r = idx >> 4;
            int c4 = (idx & 15) * 4;
            uint4 kb = *(const uint4*)&g_k[base + (size_t)(j0 + r) * An + c4];
            *(uint4*)&sK[r * LDK + c4] = kb;
            uint4 vb = *(const uint4*)&g_v[base + (size_t)(j0 + r) * An + c4];
            *(uint4*)&sV[r * LDV + c4] = vb;
        }
        __syncthreads();

        float sacc[8][4];
        #pragma unroll
        for (int nt = 0; nt < 8; ++nt)
            #pragma unroll
            for (int e = 0; e < 4; ++e) sacc[nt][e] = 0.0f;

        #pragma unroll
        for (int ks = 0; ks < 8; ++ks) {
            uint32_t kf[8][2];
            #pragma unroll
            for (int nt = 0; nt < 8; ++nt) {
                kf[nt][0] = sK[(nt * 8 + grp) * LDK + ks * 8 + qd];
                kf[nt][1] = sK[(nt * 8 + grp) * LDK + ks * 8 + qd + 4];
            }
            #pragma unroll
            for (int nt = 0; nt < 8; ++nt)
                mma_tf32_16n8k8(sacc[nt], qf[ks], kf[nt]);
        }

        if (j0 + 63 > q0) {
            #pragma unroll
            for (int nt = 0; nt < 8; ++nt) {
                int c = j0 + nt * 8 + qd * 2;
                if (c > grow0)     sacc[nt][0] = -1e30f;
                if (c + 1 > grow0) sacc[nt][1] = -1e30f;
                if (c > grow1)     sacc[nt][2] = -1e30f;
                if (c + 1 > grow1) sacc[nt][3] = -1e30f;
            }
        }

        float rm0 = -1e30f, rm1 = -1e30f;
        #pragma unroll
        for (int nt = 0; nt < 8; ++nt) {
            rm0 = fmaxf(rm0, fmaxf(sacc[nt][0], sacc[nt][1]));
            rm1 = fmaxf(rm1, fmaxf(sacc[nt][2], sacc[nt][3]));
        }
        rm0 = fmaxf(rm0, __shfl_xor_sync(0xffffffffu, rm0, 1));
        rm0 = fmaxf(rm0, __shfl_xor_sync(0xffffffffu, rm0, 2));
        rm1 = fmaxf(rm1, __shfl_xor_sync(0xffffffffu, rm1, 1));
        rm1 = fmaxf(rm1, __shfl_xor_sync(0xffffffffu, rm1, 2));

        float mn0 = fmaxf(m0r, rm0);
        float mn1 = fmaxf(m1r, rm1);
        float corr0 = __expf(m0r - mn0);
        float corr1 = __expf(m1r - mn1);
        m0r = mn0; m1r = mn1;

        float rs0 = 0.0f, rs1 = 0.0f;
        #pragma unroll
        for (int nt = 0; nt < 8; ++nt) {
            float p0 = __expf(sacc[nt][0] - mn0);
            float p1 = __expf(sacc[nt][1] - mn0);
            float p2 = __expf(sacc[nt][2] - mn1);
            float p3 = __expf(sacc[nt][3] - mn1);
            rs0 += p0 + p1;
            rs1 += p2 + p3;
            const int pc = nt * 8 + qd * 2;
            sP[r0 * LDP + pc] = f2tf32(p0);
            sP[r0 * LDP + pc + 1] = f2tf32(p1);
            sP[(r0 + 8) * LDP + pc] = f2tf32(p2);
            sP[(r0 + 8) * LDP + pc + 1] = f2tf32(p3);
        }
        rs0 += __shfl_xor_sync(0xffffffffu, rs0, 1);
        rs0 += __shfl_xor_sync(0xffffffffu, rs0, 2);
        rs1 += __shfl_xor_sync(0xffffffffu, rs1, 1);
        rs1 += __shfl_xor_sync(0xffffffffu, rs1, 2);
        l0r = l0r * corr0 + rs0;
        l1r = l1r * corr1 + rs1;

        #pragma unroll
        for (int nt = 0; nt < 8; ++nt) {
            o[nt][0] *= corr0;
            o[nt][1] *= corr0;
            o[nt][2] *= corr1;
            o[nt][3] *= corr1;
        }
        __syncwarp();

        #pragma unroll
        for (int ks = 0; ks < 8; ++ks) {
            uint32_t af[4];
            af[0] = sP[r0 * LDP + ks * 8 + qd];
            af[1] = sP[(r0 + 8) * LDP + ks * 8 + qd];
            af[2] = sP[r0 * LDP + ks * 8 + qd + 4];
            af[3] = sP[(r0 + 8) * LDP + ks * 8 + qd + 4];
            #pragma unroll
            for (int nt = 0; nt < 8; ++nt) {
                uint32_t bf[2];
                bf[0] = sV[(ks * 8 + qd) * LDV + nt * 8 + grp];
                bf[1] = sV[(ks * 8 + qd + 4) * LDV + nt * 8 + grp];
                mma_tf32_16n8k8(o[nt], af, bf);
            }
        }
        __syncthreads();
    }

    // epilogue: z tf32-rounded (consumed by out-projection MMA without cvt)
    const int b = bh >> 4;
    const int h = bh & 15;
    const float inv0 = 1.0f / l0r;
    const float inv1 = 1.0f / l1r;
    #pragma unroll
    for (int nt = 0; nt < 8; ++nt) {
        const int a = nt * 8 + qd * 2;
        float2 v0, v1;
        v0.x = f2tf32f(o[nt][0] * inv0);
        v0.y = f2tf32f(o[nt][1] * inv0);
        v1.x = f2tf32f(o[nt][2] * inv1);
        v1.y = f2tf32f(o[nt][3] * inv1);
        *(float2*)&g_z[(((size_t)b * Sn + grow0) * Hn + h) * An + a] = v0;
        *(float2*)&g_z[(((size_t)b * Sn + grow1) * Hn + h) * An + a] = v1;
    }
}

// ---------------------------------------------------------------------------
extern "C" void kernel_launch(void* const* d_in, const int* in_sizes, int n_in,
                              void* d_out, int out_size)
{
    const float* residual = (const float*)d_in[0];
    const float* Wq = (const float*)d_in[1];
    const float* Wk = (const float*)d_in[2];
    const float* Wv = (const float*)d_in[3];
    const float* Wo = (const float*)d_in[4];
    const float* bq = (const float*)d_in[5];
    const float* bk = (const float*)d_in[6];
    const float* bv = (const float*)d_in[7];
    const float* bo = (const float*)d_in[8];
    float* out = (float*)d_out;

    cudaFuncSetAttribute(flash_mma_kernel, cudaFuncAttributeMaxDynamicSharedMemorySize,
                         FLASH_SMEM_BYTES);
    cudaFuncSetAttribute(gemm_mma_kernel<0>, cudaFuncAttributeMaxDynamicSharedMemorySize,
                         GEMM_SMEM);
    cudaFuncSetAttribute(gemm_mma_kernel<1>, cudaFuncAttributeMaxDynamicSharedMemorySize,
                         GEMM_SMEM);

    // 0) tf32 pre-conversion (once per launch; ~32MB r+w)
    tf32_convert_kernel<<<1024, 256>>>(residual, 0, Mrows * Dn / 4);
    tf32_convert_kernel<<<256, 256>>>(Wq, 1, Hn * Dn * An / 4);
    tf32_convert_kernel<<<256, 256>>>(Wk, 2, Hn * Dn * An / 4);
    tf32_convert_kernel<<<256, 256>>>(Wv, 3, Hn * Dn * An / 4);
    tf32_convert_kernel<<<256, 256>>>(Wo, 4, Hn * An * Dn / 4);

    // 1) QKV projections (pure LDS+HMMA inner loop)
    gemm_mma_kernel<0><<<dim3(HA / 128, Mrows / 128, 3), 256, GEMM_SMEM>>>(
        bq, bk, bv, nullptr);

    // 2) Causal flash attention (tf32 mma.sync)
    flash_mma_kernel<<<dim3(Sn / 128, Bn * Hn), 256, FLASH_SMEM_BYTES>>>();

    // 3) Output projection
    gemm_mma_kernel<1><<<dim3(Dn / 128, Mrows / 128, 1), 256, GEMM_SMEM>>>(
        bo, nullptr, nullptr, out);
}

// round 7
// speedup vs baseline: 1.1059x; 1.1059x over previous
#include <cuda_runtime.h>
#include <cuda_bf16.h>
#include <cstdint>

// Problem dims (fixed)
constexpr int Bn = 2;
constexpr int Sn = 2048;
constexpr int Dn = 1024;
constexpr int Hn = 16;
constexpr int An = 64;
constexpr int Mrows = Bn * Sn;        // 4096
constexpr int HA = Hn * An;           // 1024

// Scratch (device globals; allocation-free). All tf32-valued fp32 bits.
__device__ __align__(256) float g_q[(size_t)Bn * Hn * Sn * An];   // [B,H,S,A] (tf32)
__device__ __align__(256) float g_k[(size_t)Bn * Hn * Sn * An];   // (tf32)
__device__ __align__(256) float g_v[(size_t)Bn * Hn * Sn * An];   // (tf32)
__device__ __align__(256) float g_z[(size_t)Bn * Sn * Hn * An];   // [B,S,H,A] (tf32)
__device__ __align__(256) float g_at[(size_t)Mrows * Dn];         // residual (tf32)
__device__ __align__(256) float g_w4[(size_t)4 * 1024 * 1024];    // Wq,Wk,Wv,Wo (tf32)

// ---------------------------------------------------------------------------
// Helpers (sm_80-baseline PTX: cp.async + mma.sync tf32; NO tcgen05)
// ---------------------------------------------------------------------------
__device__ __forceinline__ void cp_async16(uint32_t dst, const void* src) {
    asm volatile("cp.async.cg.shared.global [%0], [%1], 16;" :: "r"(dst), "l"(src) : "memory");
}
__device__ __forceinline__ uint32_t smem_u32(const void* p) {
    uint32_t a;
    asm("{ .reg .u64 t; cvta.to.shared.u64 t, %1; cvt.u32.u64 %0, t; }" : "=r"(a) : "l"(p));
    return a;
}
__device__ __forceinline__ void cp_commit() {
    asm volatile("cp.async.commit_group;" ::: "memory");
}
template <int N>
__device__ __forceinline__ void cp_wait() {
    asm volatile("cp.async.wait_group %0;" :: "n"(N) : "memory");
}
__device__ __forceinline__ uint32_t f2tf32(float x) {
    uint32_t r;
    asm("cvt.rna.tf32.f32 %0, %1;" : "=r"(r) : "f"(x));
    return r;
}
__device__ __forceinline__ float f2tf32f(float x) {
    return __uint_as_float(f2tf32(x));
}
__device__ __forceinline__ void mma_tf32_16n8k8(float* c, const uint32_t* a, const uint32_t* b) {
    asm volatile(
        "mma.sync.aligned.m16n8k8.row.col.f32.tf32.tf32.f32 "
        "{%0,%1,%2,%3}, {%4,%5,%6,%7}, {%8,%9}, {%0,%1,%2,%3};"
        : "+f"(c[0]), "+f"(c[1]), "+f"(c[2]), "+f"(c[3])
        : "r"(a[0]), "r"(a[1]), "r"(a[2]), "r"(a[3]), "r"(b[0]), "r"(b[1]));
}

// ---------------------------------------------------------------------------
// Single consolidated pre-pass: residual + Wq,Wk,Wv,Wo -> tf32 globals.
// 2M float4 total: [0,1M) residual, then 256K each for the 4 weights.
// ---------------------------------------------------------------------------
__global__ __launch_bounds__(256) void tf32_convert_all_kernel(
    const float* __restrict__ resid,
    const float* __restrict__ Wq, const float* __restrict__ Wk,
    const float* __restrict__ Wv, const float* __restrict__ Wo)
{
    constexpr int R4 = Mrows * Dn / 4;          // 1M
    constexpr int W4 = 1024 * 1024 / 4;         // 256K per weight
    int idx = blockIdx.x * 256 + threadIdx.x;
    int stride = gridDim.x * 256;
    for (int i = idx; i < R4 + 4 * W4; i += stride) {
        const float4* src;
        float4* dst;
        if (i < R4) {
            src = (const float4*)resid + i;
            dst = (float4*)g_at + i;
        } else {
            int j = i - R4;
            int w = j / W4;
            int o = j - w * W4;
            const float* S = (w == 0) ? Wq : (w == 1) ? Wk : (w == 2) ? Wv : Wo;
            src = (const float4*)S + o;
            dst = (float4*)(g_w4 + (size_t)w * (1024 * 1024)) + o;
        }
        float4 v = *src;
        v.x = f2tf32f(v.x);
        v.y = f2tf32f(v.y);
        v.z = f2tf32f(v.z);
        v.w = f2tf32f(v.w);
        *dst = v;
    }
}

// ---------------------------------------------------------------------------
// tf32 mma.sync GEMM, warp tile 64x64: block 128x128, 128 threads (4 warps
// in 2m x 2n). 3-stage cp.async ring. Pure LDS+HMMA inner loop.
// MODE 0: QKV from g_at x g_w4[z] -> g_q/g_k/g_v (tf32-rounded stores)
// MODE 1: out  from g_z  x g_w4[3] -> outp (full fp32)
// ---------------------------------------------------------------------------
constexpr int LDA = 36;
constexpr int LDB = 136;
constexpr int A_STG = 128 * LDA;
constexpr int B_STG = 32 * LDB;
constexpr int STG_FLOATS = A_STG + B_STG;
constexpr int NSTAGE = 3;
constexpr int GEMM_SMEM = NSTAGE * STG_FLOATS * 4;   // 107520
constexpr int KCHUNKS = 1024 / 32;

template<int MODE>
__global__ __launch_bounds__(128) void gemm_mma_kernel(
    const float* __restrict__ b0, const float* __restrict__ b1, const float* __restrict__ b2,
    float* __restrict__ outp)
{
    extern __shared__ __align__(16) uint32_t smem[];

    const int tid = threadIdx.x;
    const int lane = tid & 31;
    const int wid = tid >> 5;       // 0..3
    const int warp_m = wid & 1;     // 0..1 (64 rows)
    const int warp_n = wid >> 1;    // 0..1 (64 cols)
    const int grp = lane >> 2;      // 0..7
    const int qd = lane & 3;        // 0..3

    const int m0 = blockIdx.y * 128;
    const int n0 = blockIdx.x * 128;
    const int z = blockIdx.z;

    const float* A = (MODE == 0) ? (const float*)g_at : (const float*)g_z;
    const float* W = (MODE == 0) ? (g_w4 + (size_t)z * (1024 * 1024))
                                 : (g_w4 + (size_t)3 * (1024 * 1024));
    const float* bias = (MODE == 0) ? ((z == 0) ? b0 : (z == 1) ? b1 : b2) : b0;

    const uint32_t smem_base = smem_u32(smem);

    // producer: 128 threads; A: 1024 segs -> 8 each; B: 1024 segs -> 8 each
    auto produce = [&](int kc) {
        const int slot = kc % NSTAGE;
        const uint32_t sA = smem_base + (uint32_t)(slot * STG_FLOATS) * 4;
        const uint32_t sB = sA + (uint32_t)A_STG * 4;
        #pragma unroll
        for (int i = 0; i < 8; ++i) {
            int task = i * 128 + tid;
            int r = task >> 3;
            int sgm = task & 7;
            cp_async16(sA + (uint32_t)(r * LDA + sgm * 4) * 4,
                       A + (size_t)(m0 + r) * 1024 + kc * 32 + sgm * 4);
        }
        #pragma unroll
        for (int i = 0; i < 8; ++i) {
            int task = i * 128 + tid;
            int kr = task >> 5;
            int sgm = task & 31;
            int nl = sgm * 4;
            const float* src;
            if (MODE == 0) {
                int ng = n0 + nl;
                src = W + (size_t)(ng >> 6) * (Dn * An) + (size_t)(kc * 32 + kr) * An + (ng & 63);
            } else {
                src = W + (size_t)(kc * 32 + kr) * Dn + n0 + nl;
            }
            cp_async16(sB + (uint32_t)(kr * LDB + nl) * 4, src);
        }
        cp_commit();
    };

    float acc[4][8][4];
    #pragma unroll
    for (int mt = 0; mt < 4; ++mt)
        #pragma unroll
        for (int nt = 0; nt < 8; ++nt)
            #pragma unroll
            for (int e = 0; e < 4; ++e) acc[mt][nt][e] = 0.0f;

    produce(0);
    produce(1);

    for (int kc = 0; kc < KCHUNKS; ++kc) {
        cp_wait<1>();
        __syncthreads();                       // data visible; also fences slot reuse
        if (kc + 2 < KCHUNKS) produce(kc + 2);

        const int slot = kc % NSTAGE;
        const uint32_t* sA = smem + slot * STG_FLOATS;
        const uint32_t* sB = sA + A_STG;

        #pragma unroll
        for (int ks = 0; ks < 4; ++ks) {
            uint32_t af[4][4], bf[8][2];
            #pragma unroll
            for (int mt = 0; mt < 4; ++mt) {
                const int rb = warp_m * 64 + mt * 16 + grp;
                const int cb = ks * 8 + qd;
                af[mt][0] = sA[rb * LDA + cb];
                af[mt][1] = sA[(rb + 8) * LDA + cb];
                af[mt][2] = sA[rb * LDA + cb + 4];
                af[mt][3] = sA[(rb + 8) * LDA + cb + 4];
            }
            #pragma unroll
            for (int nt = 0; nt < 8; ++nt) {
                const int nb = warp_n * 64 + nt * 8 + grp;
                bf[nt][0] = sB[(ks * 8 + qd) * LDB + nb];
                bf[nt][1] = sB[(ks * 8 + qd + 4) * LDB + nb];
            }
            #pragma unroll
            for (int mt = 0; mt < 4; ++mt)
                #pragma unroll
                for (int nt = 0; nt < 8; ++nt)
                    mma_tf32_16n8k8(acc[mt][nt], af[mt], bf[nt]);
        }
        // no bottom barrier: next iteration's top barrier orders slot reuse
    }

    #pragma unroll
    for (int mt = 0; mt < 4; ++mt) {
        #pragma unroll
        for (int half = 0; half < 2; ++half) {
            const int m = m0 + warp_m * 64 + mt * 16 + grp + half * 8;
            #pragma unroll
            for (int nt = 0; nt < 8; ++nt) {
                const int n = n0 + warp_n * 64 + nt * 8 + qd * 2;
                float2 v;
                v.x = acc[mt][nt][half * 2 + 0] + bias[n];
                v.y = acc[mt][nt][half * 2 + 1] + bias[n + 1];
                if (MODE == 0) {
                    v.x = f2tf32f(v.x);
                    v.y = f2tf32f(v.y);
                    const int b = m >> 11;
                    const int s = m & 2047;
                    float* O = (z == 0) ? g_q : (z == 1) ? g_k : g_v;
                    *(float2*)&O[(((size_t)b * Hn + (n >> 6)) * Sn + s) * An + (n & 63)] = v;
                } else {
                    *(float2*)&outp[(size_t)m * Dn + n] = v;
                }
            }
        }
    }
}

// ---------------------------------------------------------------------------
// Causal flash attention (mma.sync tf32) — unchanged from R6 (proven).
// ---------------------------------------------------------------------------
constexpr int LDQ = 68;
constexpr int LDK = 68;
constexpr int LDV = 72;
constexpr int LDP = 68;
constexpr int FL_SQ = 128 * LDQ;
constexpr int FL_SK = 64 * LDK;
constexpr int FL_SV = 64 * LDV;
constexpr int FL_SP = 128 * LDP;
constexpr int FLASH_SMEM_BYTES = (FL_SQ + FL_SK + FL_SV + FL_SP) * 4;

__global__ __launch_bounds__(256) void flash_mma_kernel()
{
    extern __shared__ uint32_t sm_u[];
    uint32_t* sQ = sm_u;
    uint32_t* sK = sQ + FL_SQ;
    uint32_t* sV = sK + FL_SK;
    uint32_t* sP = sV + FL_SV;

    const int tid = threadIdx.x;
    const int lane = tid & 31;
    const int wid = tid >> 5;
    const int grp = lane >> 2;
    const int qd = lane & 3;

    const int bh = blockIdx.y;
    const size_t base = (size_t)bh * Sn * An;
    const int q0 = blockIdx.x * 128;

    for (int idx = tid; idx < 128 * 16; idx += 256) {
        int r = idx >> 4;
        int c4 = (idx & 15) * 4;
        float4 v = *(const float4*)&g_q[base + (size_t)(q0 + r) * An + c4];
        sQ[r * LDQ + c4 + 0] = __float_as_uint(v.x * 0.125f);
        sQ[r * LDQ + c4 + 1] = __float_as_uint(v.y * 0.125f);
        sQ[r * LDQ + c4 + 2] = __float_as_uint(v.z * 0.125f);
        sQ[r * LDQ + c4 + 3] = __float_as_uint(v.w * 0.125f);
    }
    __syncthreads();

    const int r0 = wid * 16 + grp;
    uint32_t qf[8][4];
    #pragma unroll
    for (int ks = 0; ks < 8; ++ks) {
        qf[ks][0] = sQ[r0 * LDQ + ks * 8 + qd];
        qf[ks][1] = sQ[(r0 + 8) * LDQ + ks * 8 + qd];
        qf[ks][2] = sQ[r0 * LDQ + ks * 8 + qd + 4];
        qf[ks][3] = sQ[(r0 + 8) * LDQ + ks * 8 + qd + 4];
    }

    float m0r = -1e30f, m1r = -1e30f, l0r = 0.0f, l1r = 0.0f;
    float o[8][4];
    #pragma unroll
    for (int nt = 0; nt < 8; ++nt)
        #pragma unroll
        for (int e = 0; e < 4; ++e) o[nt][e] = 0.0f;

    const int grow0 = q0 + r0;
    const int grow1 = grow0 + 8;

    for (int j0 = 0; j0 < q0 + 128; j0 += 64) {
        for (int idx = tid; idx < 64 * 16; idx += 256) {
            int r = idx >> 4;
            int c4 = (idx & 15) * 4;
            uint4 kb = *(const uint4*)&g_k[base + (size_t)(j0 + r) * An + c4];
            *(uint4*)&sK[r * LDK + c4] = kb;
            uint4 vb = *(const uint4*)&g_v[base + (size_t)(j0 + r) * An + c4];
            *(uint4*)&sV[r * LDV + c4] = vb;
        }
        __syncthreads();

        float sacc[8][4];
        #pragma unroll
        for (int nt = 0; nt < 8; ++nt)
            #pragma unroll
            for (int e = 0; e < 4; ++e) sacc[nt][e] = 0.0f;

        #pragma unroll
        for (int ks = 0; ks < 8; ++ks) {
            uint32_t kf[8][2];
            #pragma unroll
            for (int nt = 0; nt < 8; ++nt) {
                kf[nt][0] = sK[(nt * 8 + grp) * LDK + ks * 8 + qd];
                kf[nt][1] = sK[(nt * 8 + grp) * LDK + ks * 8 + qd + 4];
            }
            #pragma unroll
            for (int nt = 0; nt < 8; ++nt)
                mma_tf32_16n8k8(sacc[nt], qf[ks], kf[nt]);
        }

        if (j0 + 63 > q0) {
            #pragma unroll
            for (int nt = 0; nt < 8; ++nt) {
                int c = j0 + nt * 8 + qd * 2;
                if (c > grow0)     sacc[nt][0] = -1e30f;
                if (c + 1 > grow0) sacc[nt][1] = -1e30f;
                if (c > grow1)     sacc[nt][2] = -1e30f;
                if (c + 1 > grow1) sacc[nt][3] = -1e30f;
            }
        }

        float rm0 = -1e30f, rm1 = -1e30f;
        #pragma unroll
        for (int nt = 0; nt < 8; ++nt) {
            rm0 = fmaxf(rm0, fmaxf(sacc[nt][0], sacc[nt][1]));
            rm1 = fmaxf(rm1, fmaxf(sacc[nt][2], sacc[nt][3]));
        }
        rm0 = fmaxf(rm0, __shfl_xor_sync(0xffffffffu, rm0, 1));
        rm0 = fmaxf(rm0, __shfl_xor_sync(0xffffffffu, rm0, 2));
        rm1 = fmaxf(rm1, __shfl_xor_sync(0xffffffffu, rm1, 1));
        rm1 = fmaxf(rm1, __shfl_xor_sync(0xffffffffu, rm1, 2));

        float mn0 = fmaxf(m0r, rm0);
        float mn1 = fmaxf(m1r, rm1);
        float corr0 = __expf(m0r - mn0);
        float corr1 = __expf(m1r - mn1);
        m0r = mn0; m1r = mn1;

        float rs0 = 0.0f, rs1 = 0.0f;
        #pragma unroll
        for (int nt = 0; nt < 8; ++nt) {
            float p0 = __expf(sacc[nt][0] - mn0);
            float p1 = __expf(sacc[nt][1] - mn0);
            float p2 = __expf(sacc[nt][2] - mn1);
            float p3 = __expf(sacc[nt][3] - mn1);
            rs0 += p0 + p1;
            rs1 += p2 + p3;
            const int pc = nt * 8 + qd * 2;
            sP[r0 * LDP + pc] = f2tf32(p0);
            sP[r0 * LDP + pc + 1] = f2tf32(p1);
            sP[(r0 + 8) * LDP + pc] = f2tf32(p2);
            sP[(r0 + 8) * LDP + pc + 1] = f2tf32(p3);
        }
        rs0 += __shfl_xor_sync(0xffffffffu, rs0, 1);
        rs0 += __shfl_xor_sync(0xffffffffu, rs0, 2);
        rs1 += __shfl_xor_sync(0xffffffffu, rs1, 1);
        rs1 += __shfl_xor_sync(0xffffffffu, rs1, 2);
        l0r = l0r * corr0 + rs0;
        l1r = l1r * corr1 + rs1;

        #pragma unroll
        for (int nt = 0; nt < 8; ++nt) {
            o[nt][0] *= corr0;
            o[nt][1] *= corr0;
            o[nt][2] *= corr1;
            o[nt][3] *= corr1;
        }
        __syncwarp();

        #pragma unroll
        for (int ks = 0; ks < 8; ++ks) {
            uint32_t af[4];
            af[0] = sP[r0 * LDP + ks * 8 + qd];
            af[1] = sP[(r0 + 8) * LDP + ks * 8 + qd];
            af[2] = sP[r0 * LDP + ks * 8 + qd + 4];
            af[3] = sP[(r0 + 8) * LDP + ks * 8 + qd + 4];
            #pragma unroll
            for (int nt = 0; nt < 8; ++nt) {
                uint32_t bf[2];
                bf[0] = sV[(ks * 8 + qd) * LDV + nt * 8 + grp];
                bf[1] = sV[(ks * 8 + qd + 4) * LDV + nt * 8 + grp];
                mma_tf32_16n8k8(o[nt], af, bf);
            }
        }
        __syncthreads();
    }

    const int b = bh >> 4;
    const int h = bh & 15;
    const float inv0 = 1.0f / l0r;
    const float inv1 = 1.0f / l1r;
    #pragma unroll
    for (int nt = 0; nt < 8; ++nt) {
        const int a = nt * 8 + qd * 2;
        float2 v0, v1;
        v0.x = f2tf32f(o[nt][0] * inv0);
        v0.y = f2tf32f(o[nt][1] * inv0);
        v1.x = f2tf32f(o[nt][2] * inv1);
        v1.y = f2tf32f(o[nt][3] * inv1);
        *(float2*)&g_z[(((size_t)b * Sn + grow0) * Hn + h) * An + a] = v0;
        *(float2*)&g_z[(((size_t)b * Sn + grow1) * Hn + h) * An + a] = v1;
    }
}

// ---------------------------------------------------------------------------
extern "C" void kernel_launch(void* const* d_in, const int* in_sizes, int n_in,
                              void* d_out, int out_size)
{
    const float* residual = (const float*)d_in[0];
    const float* Wq = (const float*)d_in[1];
    const float* Wk = (const float*)d_in[2];
    const float* Wv = (const float*)d_in[3];
    const float* Wo = (const float*)d_in[4];
    const float* bq = (const float*)d_in[5];
    const float* bk = (const float*)d_in[6];
    const float* bv = (const float*)d_in[7];
    const float* bo = (const float*)d_in[8];
    float* out = (float*)d_out;

    cudaFuncSetAttribute(flash_mma_kernel, cudaFuncAttributeMaxDynamicSharedMemorySize,
                         FLASH_SMEM_BYTES);
    cudaFuncSetAttribute(gemm_mma_kernel<0>, cudaFuncAttributeMaxDynamicSharedMemorySize,
                         GEMM_SMEM);
    cudaFuncSetAttribute(gemm_mma_kernel<1>, cudaFuncAttributeMaxDynamicSharedMemorySize,
                         GEMM_SMEM);

    // 0) one consolidated tf32 pre-pass
    tf32_convert_all_kernel<<<1184, 256>>>(residual, Wq, Wk, Wv, Wo);

    // 1) QKV projections (warp tile 64x64, pure LDS+HMMA)
    gemm_mma_kernel<0><<<dim3(HA / 128, Mrows / 128, 3), 128, GEMM_SMEM>>>(
        bq, bk, bv, nullptr);

    // 2) Causal flash attention (tf32 mma.sync)
    flash_mma_kernel<<<dim3(Sn / 128, Bn * Hn), 256, FLASH_SMEM_BYTES>>>();

    // 3) Output projection
    gemm_mma_kernel<1><<<dim3(Dn / 128, Mrows / 128, 1), 128, GEMM_SMEM>>>(
        bo, nullptr, nullptr, out);
}

// round 8
// speedup vs baseline: 1.1458x; 1.0361x over previous
#include <cuda_runtime.h>
#include <cuda_bf16.h>
#include <cstdint>

// Problem dims (fixed)
constexpr int Bn = 2;
constexpr int Sn = 2048;
constexpr int Dn = 1024;
constexpr int Hn = 16;
constexpr int An = 64;
constexpr int Mrows = Bn * Sn;        // 4096
constexpr int HA = Hn * An;           // 1024

// Scratch (device globals; allocation-free). All tf32-valued fp32 bits.
__device__ __align__(256) float g_q[(size_t)Bn * Hn * Sn * An];   // [B,H,S,A] (tf32, pre-scaled by 1/8)
__device__ __align__(256) float g_k[(size_t)Bn * Hn * Sn * An];   // (tf32)
__device__ __align__(256) float g_v[(size_t)Bn * Hn * Sn * An];   // (tf32)
__device__ __align__(256) float g_z[(size_t)Bn * Sn * Hn * An];   // [B,S,H,A] (tf32)
__device__ __align__(256) float g_at[(size_t)Mrows * Dn];         // residual (tf32)
__device__ __align__(256) float g_w4[(size_t)4 * 1024 * 1024];    // Wq,Wk,Wv,Wo (tf32)

// ---------------------------------------------------------------------------
// Helpers (sm_80-baseline PTX: cp.async + mma.sync tf32; NO tcgen05)
// ---------------------------------------------------------------------------
__device__ __forceinline__ void cp_async16(uint32_t dst, const void* src) {
    asm volatile("cp.async.cg.shared.global [%0], [%1], 16;" :: "r"(dst), "l"(src) : "memory");
}
__device__ __forceinline__ uint32_t smem_u32(const void* p) {
    uint32_t a;
    asm("{ .reg .u64 t; cvta.to.shared.u64 t, %1; cvt.u32.u64 %0, t; }" : "=r"(a) : "l"(p));
    return a;
}
__device__ __forceinline__ void cp_commit() {
    asm volatile("cp.async.commit_group;" ::: "memory");
}
template <int N>
__device__ __forceinline__ void cp_wait() {
    asm volatile("cp.async.wait_group %0;" :: "n"(N) : "memory");
}
__device__ __forceinline__ uint32_t f2tf32(float x) {
    uint32_t r;
    asm("cvt.rna.tf32.f32 %0, %1;" : "=r"(r) : "f"(x));
    return r;
}
__device__ __forceinline__ float f2tf32f(float x) {
    return __uint_as_float(f2tf32(x));
}
__device__ __forceinline__ void mma_tf32_16n8k8(float* c, const uint32_t* a, const uint32_t* b) {
    asm volatile(
        "mma.sync.aligned.m16n8k8.row.col.f32.tf32.tf32.f32 "
        "{%0,%1,%2,%3}, {%4,%5,%6,%7}, {%8,%9}, {%0,%1,%2,%3};"
        : "+f"(c[0]), "+f"(c[1]), "+f"(c[2]), "+f"(c[3])
        : "r"(a[0]), "r"(a[1]), "r"(a[2]), "r"(a[3]), "r"(b[0]), "r"(b[1]));
}

// ---------------------------------------------------------------------------
// Consolidated tf32 pre-pass (unchanged from R7)
// ---------------------------------------------------------------------------
__global__ __launch_bounds__(256) void tf32_convert_all_kernel(
    const float* __restrict__ resid,
    const float* __restrict__ Wq, const float* __restrict__ Wk,
    const float* __restrict__ Wv, const float* __restrict__ Wo)
{
    constexpr int R4 = Mrows * Dn / 4;
    constexpr int W4 = 1024 * 1024 / 4;
    int idx = blockIdx.x * 256 + threadIdx.x;
    int stride = gridDim.x * 256;
    for (int i = idx; i < R4 + 4 * W4; i += stride) {
        const float4* src;
        float4* dst;
        if (i < R4) {
            src = (const float4*)resid + i;
            dst = (float4*)g_at + i;
        } else {
            int j = i - R4;
            int w = j / W4;
            int o = j - w * W4;
            const float* S = (w == 0) ? Wq : (w == 1) ? Wk : (w == 2) ? Wv : Wo;
            src = (const float4*)S + o;
            dst = (float4*)(g_w4 + (size_t)w * (1024 * 1024)) + o;
        }
        float4 v = *src;
        v.x = f2tf32f(v.x);
        v.y = f2tf32f(v.y);
        v.z = f2tf32f(v.z);
        v.w = f2tf32f(v.w);
        *dst = v;
    }
}

// ---------------------------------------------------------------------------
// tf32 mma.sync GEMM (R7 config; MODE 0 q-output pre-scaled by 1/8)
// ---------------------------------------------------------------------------
constexpr int LDA = 36;
constexpr int LDB = 136;
constexpr int A_STG = 128 * LDA;
constexpr int B_STG = 32 * LDB;
constexpr int STG_FLOATS = A_STG + B_STG;
constexpr int NSTAGE = 3;
constexpr int GEMM_SMEM = NSTAGE * STG_FLOATS * 4;
constexpr int KCHUNKS = 1024 / 32;

template<int MODE>
__global__ __launch_bounds__(128) void gemm_mma_kernel(
    const float* __restrict__ b0, const float* __restrict__ b1, const float* __restrict__ b2,
    float* __restrict__ outp)
{
    extern __shared__ __align__(16) uint32_t smem[];

    const int tid = threadIdx.x;
    const int lane = tid & 31;
    const int wid = tid >> 5;
    const int warp_m = wid & 1;
    const int warp_n = wid >> 1;
    const int grp = lane >> 2;
    const int qd = lane & 3;

    const int m0 = blockIdx.y * 128;
    const int n0 = blockIdx.x * 128;
    const int z = blockIdx.z;

    const float* A = (MODE == 0) ? (const float*)g_at : (const float*)g_z;
    const float* W = (MODE == 0) ? (g_w4 + (size_t)z * (1024 * 1024))
                                 : (g_w4 + (size_t)3 * (1024 * 1024));
    const float* bias = (MODE == 0) ? ((z == 0) ? b0 : (z == 1) ? b1 : b2) : b0;

    const uint32_t smem_base = smem_u32(smem);

    auto produce = [&](int kc) {
        const int slot = kc % NSTAGE;
        const uint32_t sA = smem_base + (uint32_t)(slot * STG_FLOATS) * 4;
        const uint32_t sB = sA + (uint32_t)A_STG * 4;
        #pragma unroll
        for (int i = 0; i < 8; ++i) {
            int task = i * 128 + tid;
            int r = task >> 3;
            int sgm = task & 7;
            cp_async16(sA + (uint32_t)(r * LDA + sgm * 4) * 4,
                       A + (size_t)(m0 + r) * 1024 + kc * 32 + sgm * 4);
        }
        #pragma unroll
        for (int i = 0; i < 8; ++i) {
            int task = i * 128 + tid;
            int kr = task >> 5;
            int sgm = task & 31;
            int nl = sgm * 4;
            const float* src;
            if (MODE == 0) {
                int ng = n0 + nl;
                src = W + (size_t)(ng >> 6) * (Dn * An) + (size_t)(kc * 32 + kr) * An + (ng & 63);
            } else {
                src = W + (size_t)(kc * 32 + kr) * Dn + n0 + nl;
            }
            cp_async16(sB + (uint32_t)(kr * LDB + nl) * 4, src);
        }
        cp_commit();
    };

    float acc[4][8][4];
    #pragma unroll
    for (int mt = 0; mt < 4; ++mt)
        #pragma unroll
        for (int nt = 0; nt < 8; ++nt)
            #pragma unroll
            for (int e = 0; e < 4; ++e) acc[mt][nt][e] = 0.0f;

    produce(0);
    produce(1);

    for (int kc = 0; kc < KCHUNKS; ++kc) {
        cp_wait<1>();
        __syncthreads();
        if (kc + 2 < KCHUNKS) produce(kc + 2);

        const int slot = kc % NSTAGE;
        const uint32_t* sA = smem + slot * STG_FLOATS;
        const uint32_t* sB = sA + A_STG;

        #pragma unroll
        for (int ks = 0; ks < 4; ++ks) {
            uint32_t af[4][4], bf[8][2];
            #pragma unroll
            for (int mt = 0; mt < 4; ++mt) {
                const int rb = warp_m * 64 + mt * 16 + grp;
                const int cb = ks * 8 + qd;
                af[mt][0] = sA[rb * LDA + cb];
                af[mt][1] = sA[(rb + 8) * LDA + cb];
                af[mt][2] = sA[rb * LDA + cb + 4];
                af[mt][3] = sA[(rb + 8) * LDA + cb + 4];
            }
            #pragma unroll
            for (int nt = 0; nt < 8; ++nt) {
                const int nb = warp_n * 64 + nt * 8 + grp;
                bf[nt][0] = sB[(ks * 8 + qd) * LDB + nb];
                bf[nt][1] = sB[(ks * 8 + qd + 4) * LDB + nb];
            }
            #pragma unroll
            for (int mt = 0; mt < 4; ++mt)
                #pragma unroll
                for (int nt = 0; nt < 8; ++nt)
                    mma_tf32_16n8k8(acc[mt][nt], af[mt], bf[nt]);
        }
    }

    #pragma unroll
    for (int mt = 0; mt < 4; ++mt) {
        #pragma unroll
        for (int half = 0; half < 2; ++half) {
            const int m = m0 + warp_m * 64 + mt * 16 + grp + half * 8;
            #pragma unroll
            for (int nt = 0; nt < 8; ++nt) {
                const int n = n0 + warp_n * 64 + nt * 8 + qd * 2;
                float2 v;
                v.x = acc[mt][nt][half * 2 + 0] + bias[n];
                v.y = acc[mt][nt][half * 2 + 1] + bias[n + 1];
                if (MODE == 0) {
                    if (z == 0) {                 // fold softmax scale into q
                        v.x *= 0.125f;
                        v.y *= 0.125f;
                    }
                    v.x = f2tf32f(v.x);
                    v.y = f2tf32f(v.y);
                    const int b = m >> 11;
                    const int s = m & 2047;
                    float* O = (z == 0) ? g_q : (z == 1) ? g_k : g_v;
                    *(float2*)&O[(((size_t)b * Hn + (n >> 6)) * Sn + s) * An + (n & 63)] = v;
                } else {
                    *(float2*)&outp[(size_t)m * Dn + n] = v;
                }
            }
        }
    }
}

// ---------------------------------------------------------------------------
// Causal flash attention (mma.sync tf32) with cp.async double-buffered K/V.
// SMEM layout (u32): stage0 KV [8960] | stage1 KV [8960] (aliases Q fill) |
//                    P [8704].  Total 26624 u32 = 104 KB -> 2 CTAs/SM.
// ---------------------------------------------------------------------------
constexpr int LDQ = 68;
constexpr int LDK = 68;
constexpr int LDV = 72;
constexpr int LDP = 68;
constexpr int KV_K = 64 * LDK;          // 4352
constexpr int KV_STG = KV_K + 64 * LDV; // 8960
constexpr int FLASH_SMEM_BYTES = (2 * KV_STG + 128 * LDP) * 4;  // 106496

__global__ __launch_bounds__(256) void flash_mma_kernel()
{
    extern __shared__ uint32_t sm_u[];
    uint32_t* sP = sm_u + 2 * KV_STG;
    uint32_t* sQ = sm_u + KV_STG;       // transient alias of stage 1

    const int tid = threadIdx.x;
    const int lane = tid & 31;
    const int wid = tid >> 5;
    const int grp = lane >> 2;
    const int qd = lane & 3;

    const int bh = blockIdx.y;
    const size_t base = (size_t)bh * Sn * An;
    const int q0 = blockIdx.x * 128;
    const uint32_t smem_base = smem_u32(sm_u);

    // producer: cp.async tile t (64 kv rows) into stage t&1
    auto produce = [&](int t) {
        const uint32_t sK = smem_base + (uint32_t)((t & 1) * KV_STG) * 4;
        const uint32_t sV = sK + (uint32_t)KV_K * 4;
        const int j0 = t * 64;
        #pragma unroll
        for (int i = 0; i < 4; ++i) {
            int idx = i * 256 + tid;        // 1024 float4 tasks
            int r = idx >> 4;
            int c4 = (idx & 15) * 4;
            cp_async16(sK + (uint32_t)(r * LDK + c4) * 4,
                       &g_k[base + (size_t)(j0 + r) * An + c4]);
            cp_async16(sV + (uint32_t)(r * LDV + c4) * 4,
                       &g_v[base + (size_t)(j0 + r) * An + c4]);
        }
        cp_commit();
    };

    produce(0);

    // Q fill: pure copy (already tf32, pre-scaled by 1/8 in GEMM epilogue)
    for (int idx = tid; idx < 128 * 16; idx += 256) {
        int r = idx >> 4;
        int c4 = (idx & 15) * 4;
        *(uint4*)&sQ[r * LDQ + c4] = *(const uint4*)&g_q[base + (size_t)(q0 + r) * An + c4];
    }
    __syncthreads();

    const int r0 = wid * 16 + grp;
    uint32_t qf[8][4];
    #pragma unroll
    for (int ks = 0; ks < 8; ++ks) {
        qf[ks][0] = sQ[r0 * LDQ + ks * 8 + qd];
        qf[ks][1] = sQ[(r0 + 8) * LDQ + ks * 8 + qd];
        qf[ks][2] = sQ[r0 * LDQ + ks * 8 + qd + 4];
        qf[ks][3] = sQ[(r0 + 8) * LDQ + ks * 8 + qd + 4];
    }
    __syncthreads();      // Q reads done before stage1 cp.async overwrites
    produce(1);

    float m0r = -1e30f, m1r = -1e30f, l0r = 0.0f, l1r = 0.0f;
    float o[8][4];
    #pragma unroll
    for (int nt = 0; nt < 8; ++nt)
        #pragma unroll
        for (int e = 0; e < 4; ++e) o[nt][e] = 0.0f;

    const int grow0 = q0 + r0;
    const int grow1 = grow0 + 8;
    const int ntiles = (q0 + 128) / 64;

    for (int t = 0; t < ntiles; ++t) {
        cp_wait<1>();          // stage t resident (t+1 may still fly)
        __syncthreads();

        const uint32_t* sK = sm_u + (t & 1) * KV_STG;
        const uint32_t* sV = sK + KV_K;
        const int j0 = t * 64;

        float sacc[8][4];
        #pragma unroll
        for (int nt = 0; nt < 8; ++nt)
            #pragma unroll
            for (int e = 0; e < 4; ++e) sacc[nt][e] = 0.0f;

        #pragma unroll
        for (int ks = 0; ks < 8; ++ks) {
            uint32_t kf[8][2];
            #pragma unroll
            for (int nt = 0; nt < 8; ++nt) {
                kf[nt][0] = sK[(nt * 8 + grp) * LDK + ks * 8 + qd];
                kf[nt][1] = sK[(nt * 8 + grp) * LDK + ks * 8 + qd + 4];
            }
            #pragma unroll
            for (int nt = 0; nt < 8; ++nt)
                mma_tf32_16n8k8(sacc[nt], qf[ks], kf[nt]);
        }

        if (j0 + 63 > q0) {
            #pragma unroll
            for (int nt = 0; nt < 8; ++nt) {
                int c = j0 + nt * 8 + qd * 2;
                if (c > grow0)     sacc[nt][0] = -1e30f;
                if (c + 1 > grow0) sacc[nt][1] = -1e30f;
                if (c > grow1)     sacc[nt][2] = -1e30f;
                if (c + 1 > grow1) sacc[nt][3] = -1e30f;
            }
        }

        float rm0 = -1e30f, rm1 = -1e30f;
        #pragma unroll
        for (int nt = 0; nt < 8; ++nt) {
            rm0 = fmaxf(rm0, fmaxf(sacc[nt][0], sacc[nt][1]));
            rm1 = fmaxf(rm1, fmaxf(sacc[nt][2], sacc[nt][3]));
        }
        rm0 = fmaxf(rm0, __shfl_xor_sync(0xffffffffu, rm0, 1));
        rm0 = fmaxf(rm0, __shfl_xor_sync(0xffffffffu, rm0, 2));
        rm1 = fmaxf(rm1, __shfl_xor_sync(0xffffffffu, rm1, 1));
        rm1 = fmaxf(rm1, __shfl_xor_sync(0xffffffffu, rm1, 2));

        float mn0 = fmaxf(m0r, rm0);
        float mn1 = fmaxf(m1r, rm1);
        float corr0 = __expf(m0r - mn0);
        float corr1 = __expf(m1r - mn1);
        m0r = mn0; m1r = mn1;

        float rs0 = 0.0f, rs1 = 0.0f;
        #pragma unroll
        for (int nt = 0; nt < 8; ++nt) {
            float p0 = __expf(sacc[nt][0] - mn0);
            float p1 = __expf(sacc[nt][1] - mn0);
            float p2 = __expf(sacc[nt][2] - mn1);
            float p3 = __expf(sacc[nt][3] - mn1);
            rs0 += p0 + p1;
            rs1 += p2 + p3;
            const int pc = nt * 8 + qd * 2;
            sP[r0 * LDP + pc] = f2tf32(p0);
            sP[r0 * LDP + pc + 1] = f2tf32(p1);
            sP[(r0 + 8) * LDP + pc] = f2tf32(p2);
            sP[(r0 + 8) * LDP + pc + 1] = f2tf32(p3);
        }
        rs0 += __shfl_xor_sync(0xffffffffu, rs0, 1);
        rs0 += __shfl_xor_sync(0xffffffffu, rs0, 2);
        rs1 += __shfl_xor_sync(0xffffffffu, rs1, 1);
        rs1 += __shfl_xor_sync(0xffffffffu, rs1, 2);
        l0r = l0r * corr0 + rs0;
        l1r = l1r * corr1 + rs1;

        #pragma unroll
        for (int nt = 0; nt < 8; ++nt) {
            o[nt][0] *= corr0;
            o[nt][1] *= corr0;
            o[nt][2] *= corr1;
            o[nt][3] *= corr1;
        }
        __syncwarp();

        #pragma unroll
        for (int ks = 0; ks < 8; ++ks) {
            uint32_t af[4];
            af[0] = sP[r0 * LDP + ks * 8 + qd];
            af[1] = sP[(r0 + 8) * LDP + ks * 8 + qd];
            af[2] = sP[r0 * LDP + ks * 8 + qd + 4];
            af[3] = sP[(r0 + 8) * LDP + ks * 8 + qd + 4];
            #pragma unroll
            for (int nt = 0; nt < 8; ++nt) {
                uint32_t bf[2];
                bf[0] = sV[(ks * 8 + qd) * LDV + nt * 8 + grp];
                bf[1] = sV[(ks * 8 + qd + 4) * LDV + nt * 8 + grp];
                mma_tf32_16n8k8(o[nt], af, bf);
            }
        }

        __syncthreads();                     // stage t fully consumed
        if (t + 2 < ntiles) produce(t + 2);  // refill freed slot
    }

    const int b = bh >> 4;
    const int h = bh & 15;
    const float inv0 = 1.0f / l0r;
    const float inv1 = 1.0f / l1r;
    #pragma unroll
    for (int nt = 0; nt < 8; ++nt) {
        const int a = nt * 8 + qd * 2;
        float2 v0, v1;
        v0.x = f2tf32f(o[nt][0] * inv0);
        v0.y = f2tf32f(o[nt][1] * inv0);
        v1.x = f2tf32f(o[nt][2] * inv1);
        v1.y = f2tf32f(o[nt][3] * inv1);
        *(float2*)&g_z[(((size_t)b * Sn + grow0) * Hn + h) * An + a] = v0;
        *(float2*)&g_z[(((size_t)b * Sn + grow1) * Hn + h) * An + a] = v1;
    }
}

// ---------------------------------------------------------------------------
extern "C" void kernel_launch(void* const* d_in, const int* in_sizes, int n_in,
                              void* d_out, int out_size)
{
    const float* residual = (const float*)d_in[0];
    const float* Wq = (const float*)d_in[1];
    const float* Wk = (const float*)d_in[2];
    const float* Wv = (const float*)d_in[3];
    const float* Wo = (const float*)d_in[4];
    const float* bq = (const float*)d_in[5];
    const float* bk = (const float*)d_in[6];
    const float* bv = (const float*)d_in[7];
    const float* bo = (const float*)d_in[8];
    float* out = (float*)d_out;

    cudaFuncSetAttribute(flash_mma_kernel, cudaFuncAttributeMaxDynamicSharedMemorySize,
                         FLASH_SMEM_BYTES);
    cudaFuncSetAttribute(gemm_mma_kernel<0>, cudaFuncAttributeMaxDynamicSharedMemorySize,
                         GEMM_SMEM);
    cudaFuncSetAttribute(gemm_mma_kernel<1>, cudaFuncAttributeMaxDynamicSharedMemorySize,
                         GEMM_SMEM);

    // 0) tf32 pre-pass
    tf32_convert_all_kernel<<<1184, 256>>>(residual, Wq, Wk, Wv, Wo);

    // 1) QKV projections (q pre-scaled by 1/8 in epilogue)
    gemm_mma_kernel<0><<<dim3(HA / 128, Mrows / 128, 3), 128, GEMM_SMEM>>>(
        bq, bk, bv, nullptr);

    // 2) Causal flash attention (double-buffered K/V)
    flash_mma_kernel<<<dim3(Sn / 128, Bn * Hn), 256, FLASH_SMEM_BYTES>>>();

    // 3) Output projection
    gemm_mma_kernel<1><<<dim3(Dn / 128, Mrows / 128, 1), 128, GEMM_SMEM>>>(
        bo, nullptr, nullptr, out);
}

// round 9
// speedup vs baseline: 1.8507x; 1.6152x over previous
#include <cuda_runtime.h>
#include <cuda_fp16.h>
#include <cstdint>

// Problem dims (fixed)
constexpr int Bn = 2;
constexpr int Sn = 2048;
constexpr int Dn = 1024;
constexpr int Hn = 16;
constexpr int An = 64;
constexpr int Mrows = Bn * Sn;        // 4096
constexpr int HA = Hn * An;           // 1024

// Scratch (device globals; allocation-free), fp16 operands
__device__ __align__(256) __half g_qh[(size_t)Bn * Hn * Sn * An];  // [b,h,s,a], pre-scaled 1/8
__device__ __align__(256) __half g_kh[(size_t)Bn * Hn * Sn * An];  // [b,h,s,a]
__device__ __align__(256) __half g_vh[(size_t)Bn * Hn * Sn * An];  // [b,h,a,s]  (transposed!)
__device__ __align__(256) __half g_zh[(size_t)Bn * Sn * Hn * An];  // [b,s,h,a]
__device__ __align__(256) __half g_ath[(size_t)Mrows * Dn];        // residual fp16 [m][k]
__device__ __align__(256) __half g_wh[(size_t)4 * 1024 * 1024];    // weights fp16 [n][k] (transposed)

// ---------------------------------------------------------------------------
// Helpers (sm_80-baseline PTX: cp.async + mma.sync f16)
// ---------------------------------------------------------------------------
__device__ __forceinline__ void cp_async16(uint32_t dst, const void* src) {
    asm volatile("cp.async.cg.shared.global [%0], [%1], 16;" :: "r"(dst), "l"(src) : "memory");
}
__device__ __forceinline__ uint32_t smem_u32(const void* p) {
    uint32_t a;
    asm("{ .reg .u64 t; cvta.to.shared.u64 t, %1; cvt.u32.u64 %0, t; }" : "=r"(a) : "l"(p));
    return a;
}
__device__ __forceinline__ void cp_commit() {
    asm volatile("cp.async.commit_group;" ::: "memory");
}
template <int N>
__device__ __forceinline__ void cp_wait() {
    asm volatile("cp.async.wait_group %0;" :: "n"(N) : "memory");
}
__device__ __forceinline__ void mma_f16_16n8k16(float* c, const uint32_t* a, const uint32_t* b) {
    asm volatile(
        "mma.sync.aligned.m16n8k16.row.col.f32.f16.f16.f32 "
        "{%0,%1,%2,%3}, {%4,%5,%6,%7}, {%8,%9}, {%0,%1,%2,%3};"
        : "+f"(c[0]), "+f"(c[1]), "+f"(c[2]), "+f"(c[3])
        : "r"(a[0]), "r"(a[1]), "r"(a[2]), "r"(a[3]), "r"(b[0]), "r"(b[1]));
}
__device__ __forceinline__ uint32_t pack_h2(float x, float y) {
    __half2 h = __floats2half2_rn(x, y);
    return *(uint32_t*)&h;
}

// ---------------------------------------------------------------------------
// Prepass 1: residual fp32 -> fp16 [m][k]
// ---------------------------------------------------------------------------
__global__ __launch_bounds__(256) void conv_resid_kernel(const float* __restrict__ src)
{
    constexpr int N4 = Mrows * Dn / 4;
    int idx = blockIdx.x * 256 + threadIdx.x;
    int stride = gridDim.x * 256;
    for (int i = idx; i < N4; i += stride) {
        float4 v = ((const float4*)src)[i];
        uint2 o;
        o.x = pack_h2(v.x, v.y);
        o.y = pack_h2(v.z, v.w);
        ((uint2*)g_ath)[i] = o;
    }
}

// ---------------------------------------------------------------------------
// Prepass 2: QKV weights [h][d][a] fp32 -> g_wh[w][n=h*64+a][k=d] fp16
// grid (d/32, a-tiles=2, 48=w*16+h), block (32,8)
// ---------------------------------------------------------------------------
__global__ void transpose_qkv_kernel(const float* __restrict__ Wq,
                                     const float* __restrict__ Wk,
                                     const float* __restrict__ Wv)
{
    __shared__ float t[32][33];
    const int w = blockIdx.z / 16;
    const int h = blockIdx.z % 16;
    const float* S = (w == 0) ? Wq : (w == 1) ? Wk : Wv;
    S += (size_t)h * Dn * An;
    __half* D = g_wh + (size_t)w * (1024 * 1024) + (size_t)h * 64 * 1024;
    const int d0 = blockIdx.x * 32;
    const int a0 = blockIdx.y * 32;
    #pragma unroll
    for (int i = 0; i < 4; ++i)
        t[threadIdx.y + i * 8][threadIdx.x] = S[(size_t)(d0 + threadIdx.y + i * 8) * An + a0 + threadIdx.x];
    __syncthreads();
    #pragma unroll
    for (int i = 0; i < 4; ++i)
        D[(size_t)(a0 + threadIdx.y + i * 8) * 1024 + d0 + threadIdx.x] =
            __float2half_rn(t[threadIdx.x][threadIdx.y + i * 8]);
}

// Prepass 3: Wo [k=ha][n=d] fp32 -> g_wh[3][n=d][k=ha] fp16. grid (32,32)
__global__ void transpose_wo_kernel(const float* __restrict__ Wo)
{
    __shared__ float t[32][33];
    __half* D = g_wh + (size_t)3 * (1024 * 1024);
    const int k0 = blockIdx.x * 32;
    const int n0 = blockIdx.y * 32;
    #pragma unroll
    for (int i = 0; i < 4; ++i)
        t[threadIdx.y + i * 8][threadIdx.x] = Wo[(size_t)(k0 + threadIdx.y + i * 8) * Dn + n0 + threadIdx.x];
    __syncthreads();
    #pragma unroll
    for (int i = 0; i < 4; ++i)
        D[(size_t)(n0 + threadIdx.y + i * 8) * 1024 + k0 + threadIdx.x] =
            __float2half_rn(t[threadIdx.x][threadIdx.y + i * 8]);
}

// ---------------------------------------------------------------------------
// fp16 mma.sync GEMM: C[4096,1024] = A[m][k] x W[n][k]^T + bias
// BM=128 BN=128 BK=32, 128 threads (4 warps 2m x 2n), warp tile 64x64.
// MODE 0: QKV -> g_qh (scaled 1/8) / g_kh / g_vh (transposed store)
// MODE 1: out-projection from g_zh -> fp32 outp
// ---------------------------------------------------------------------------
constexpr int LDAW = 20;   // A smem pitch in u32 words (40 halfs)
constexpr int A_STG_B = 128 * 80;              // bytes (80 B/row)
constexpr int STG_B = 2 * A_STG_B;             // A + B per stage = 20480
constexpr int NSTAGE = 3;
constexpr int GEMM_SMEM = NSTAGE * STG_B;      // 61440
constexpr int KCHUNKS = 1024 / 32;

template<int MODE>
__global__ __launch_bounds__(128) void gemm_mma_kernel(
    const float* __restrict__ b0, const float* __restrict__ b1, const float* __restrict__ b2,
    float* __restrict__ outp)
{
    extern __shared__ __align__(16) uint32_t smem[];

    const int tid = threadIdx.x;
    const int lane = tid & 31;
    const int wid = tid >> 5;
    const int warp_m = wid & 1;
    const int warp_n = wid >> 1;
    const int grp = lane >> 2;
    const int qd = lane & 3;

    const int m0 = blockIdx.y * 128;
    const int n0 = blockIdx.x * 128;
    const int z = blockIdx.z;

    const __half* A = (MODE == 0) ? g_ath : g_zh;
    const __half* W = (MODE == 0) ? (g_wh + (size_t)z * (1024 * 1024))
                                  : (g_wh + (size_t)3 * (1024 * 1024));
    const float* bias = (MODE == 0) ? ((z == 0) ? b0 : (z == 1) ? b1 : b2) : b0;

    const uint32_t smem_base = smem_u32(smem);

    auto produce = [&](int kc) {
        const int slot = kc % NSTAGE;
        const uint32_t sA = smem_base + (uint32_t)(slot * STG_B);
        const uint32_t sB = sA + (uint32_t)A_STG_B;
        #pragma unroll
        for (int i = 0; i < 4; ++i) {                 // A: 512 16B segs
            int task = i * 128 + tid;
            int r = task >> 2;
            int seg = task & 3;
            cp_async16(sA + (uint32_t)(r * 80 + seg * 16),
                       A + (size_t)(m0 + r) * 1024 + kc * 32 + seg * 8);
        }
        #pragma unroll
        for (int i = 0; i < 4; ++i) {                 // B: 512 16B segs
            int task = i * 128 + tid;
            int n = task >> 2;
            int seg = task & 3;
            cp_async16(sB + (uint32_t)(n * 80 + seg * 16),
                       W + (size_t)(n0 + n) * 1024 + kc * 32 + seg * 8);
        }
        cp_commit();
    };

    float acc[4][8][4];
    #pragma unroll
    for (int mt = 0; mt < 4; ++mt)
        #pragma unroll
        for (int nt = 0; nt < 8; ++nt)
            #pragma unroll
            for (int e = 0; e < 4; ++e) acc[mt][nt][e] = 0.0f;

    produce(0);
    produce(1);

    for (int kc = 0; kc < KCHUNKS; ++kc) {
        cp_wait<1>();
        __syncthreads();
        if (kc + 2 < KCHUNKS) produce(kc + 2);

        const uint32_t* sA = smem + (kc % NSTAGE) * (STG_B / 4);
        const uint32_t* sB = sA + (A_STG_B / 4);

        #pragma unroll
        for (int ks = 0; ks < 2; ++ks) {              // 2 x k16 per 32-chunk
            uint32_t af[4][4], bf[8][2];
            #pragma unroll
            for (int mt = 0; mt < 4; ++mt) {
                const int r = warp_m * 64 + mt * 16 + grp;
                const int w0 = ks * 8 + qd;
                af[mt][0] = sA[r * LDAW + w0];
                af[mt][1] = sA[(r + 8) * LDAW + w0];
                af[mt][2] = sA[r * LDAW + w0 + 4];
                af[mt][3] = sA[(r + 8) * LDAW + w0 + 4];
            }
            #pragma unroll
            for (int nt = 0; nt < 8; ++nt) {
                const int n = warp_n * 64 + nt * 8 + grp;
                bf[nt][0] = sB[n * LDAW + ks * 8 + qd];
                bf[nt][1] = sB[n * LDAW + ks * 8 + qd + 4];
            }
            #pragma unroll
            for (int mt = 0; mt < 4; ++mt)
                #pragma unroll
                for (int nt = 0; nt < 8; ++nt)
                    mma_f16_16n8k16(acc[mt][nt], af[mt], bf[nt]);
        }
    }

    #pragma unroll
    for (int mt = 0; mt < 4; ++mt) {
        #pragma unroll
        for (int half = 0; half < 2; ++half) {
            const int m = m0 + warp_m * 64 + mt * 16 + grp + half * 8;
            #pragma unroll
            for (int nt = 0; nt < 8; ++nt) {
                const int n = n0 + warp_n * 64 + nt * 8 + qd * 2;
                float vx = acc[mt][nt][half * 2 + 0] + bias[n];
                float vy = acc[mt][nt][half * 2 + 1] + bias[n + 1];
                if (MODE == 0) {
                    const int b = m >> 11;
                    const int s = m & 2047;
                    const int h = n >> 6;
                    const int a = n & 63;
                    if (z == 0) {
                        vx *= 0.125f; vy *= 0.125f;
                        uint32_t p = pack_h2(vx, vy);
                        *(uint32_t*)&g_qh[(((size_t)b * Hn + h) * Sn + s) * An + a] = p;
                    } else if (z == 1) {
                        uint32_t p = pack_h2(vx, vy);
                        *(uint32_t*)&g_kh[(((size_t)b * Hn + h) * Sn + s) * An + a] = p;
                    } else {
                        // v transposed: [b,h,a,s]
                        __half* Vd = g_vh + (((size_t)b * Hn + h) * An) * Sn;
                        Vd[(size_t)a * Sn + s] = __float2half_rn(vx);
                        Vd[(size_t)(a + 1) * Sn + s] = __float2half_rn(vy);
                    }
                } else {
                    float2 v2 = {vx, vy};
                    *(float2*)&outp[(size_t)m * Dn + n] = v2;
                }
            }
        }
    }
}

// ---------------------------------------------------------------------------
// Causal flash attention, fp16 m16n8k16, cp.async double-buffered K/V.
// Pitches: 72 halfs (36 words). SMEM: 2 KV stages (18432 B each; Q aliases
// stage 1 transiently) + P (18432 B) = 55296 B.
// ---------------------------------------------------------------------------
constexpr int FPW = 36;                 // pitch in u32 words
constexpr int K_STG_B = 64 * 144;       // 9216
constexpr int KV_STG_B = 2 * K_STG_B;   // 18432
constexpr int FLASH_SMEM_BYTES = 2 * KV_STG_B + 128 * 144;   // 55296

__global__ __launch_bounds__(256) void flash_mma_kernel()
{
    extern __shared__ uint32_t sm_u[];
    uint32_t* sP = sm_u + (2 * KV_STG_B) / 4;
    uint32_t* sQ = sm_u + KV_STG_B / 4;      // transient alias of stage 1

    const int tid = threadIdx.x;
    const int lane = tid & 31;
    const int wid = tid >> 5;
    const int grp = lane >> 2;
    const int qd = lane & 3;

    const int bh = blockIdx.y;
    const size_t base = (size_t)bh * Sn * An;   // same for q,k (s-major) and v (a-major)
    const int q0 = blockIdx.x * 128;
    const uint32_t smem_base = smem_u32(sm_u);

    auto produce = [&](int t) {
        const uint32_t sK = smem_base + (uint32_t)((t & 1) * KV_STG_B);
        const uint32_t sV = sK + (uint32_t)K_STG_B;
        const int j0 = t * 64;
        #pragma unroll
        for (int i = 0; i < 2; ++i) {            // K: 512 segs
            int idx = i * 256 + tid;
            int r = idx >> 3;
            int seg = idx & 7;
            cp_async16(sK + (uint32_t)(r * 144 + seg * 16),
                       g_kh + base + (size_t)(j0 + r) * An + seg * 8);
        }
        #pragma unroll
        for (int i = 0; i < 2; ++i) {            // V (a-major): 512 segs
            int idx = i * 256 + tid;
            int a = idx >> 3;
            int seg = idx & 7;
            cp_async16(sV + (uint32_t)(a * 144 + seg * 16),
                       g_vh + base + (size_t)a * Sn + j0 + seg * 8);
        }
        cp_commit();
    };

    produce(0);

    // Q fill via cp.async into stage-1 alias
    {
        const uint32_t sQb = smem_base + (uint32_t)KV_STG_B;
        #pragma unroll
        for (int i = 0; i < 4; ++i) {
            int idx = i * 256 + tid;
            int r = idx >> 3;
            int seg = idx & 7;
            cp_async16(sQb + (uint32_t)(r * 144 + seg * 16),
                       g_qh + base + (size_t)(q0 + r) * An + seg * 8);
        }
        cp_commit();
    }
    cp_wait<0>();
    __syncthreads();

    const int r0 = wid * 16 + grp;
    uint32_t qf[4][4];
    #pragma unroll
    for (int ks = 0; ks < 4; ++ks) {
        qf[ks][0] = sQ[r0 * FPW + ks * 8 + qd];
        qf[ks][1] = sQ[(r0 + 8) * FPW + ks * 8 + qd];
        qf[ks][2] = sQ[r0 * FPW + ks * 8 + qd + 4];
        qf[ks][3] = sQ[(r0 + 8) * FPW + ks * 8 + qd + 4];
    }
    __syncthreads();
    produce(1);

    float m0r = -1e30f, m1r = -1e30f, l0r = 0.0f, l1r = 0.0f;
    float o[8][4];
    #pragma unroll
    for (int nt = 0; nt < 8; ++nt)
        #pragma unroll
        for (int e = 0; e < 4; ++e) o[nt][e] = 0.0f;

    const int grow0 = q0 + r0;
    const int grow1 = grow0 + 8;
    const int ntiles = (q0 + 128) / 64;

    for (int t = 0; t < ntiles; ++t) {
        cp_wait<1>();
        __syncthreads();

        const uint32_t* sK = sm_u + (t & 1) * (KV_STG_B / 4);
        const uint32_t* sV = sK + (K_STG_B / 4);
        const int j0 = t * 64;

        float sacc[8][4];
        #pragma unroll
        for (int nt = 0; nt < 8; ++nt)
            #pragma unroll
            for (int e = 0; e < 4; ++e) sacc[nt][e] = 0.0f;

        #pragma unroll
        for (int ks = 0; ks < 4; ++ks) {
            uint32_t kf[8][2];
            #pragma unroll
            for (int nt = 0; nt < 8; ++nt) {
                kf[nt][0] = sK[(nt * 8 + grp) * FPW + ks * 8 + qd];
                kf[nt][1] = sK[(nt * 8 + grp) * FPW + ks * 8 + qd + 4];
            }
            #pragma unroll
            for (int nt = 0; nt < 8; ++nt)
                mma_f16_16n8k16(sacc[nt], qf[ks], kf[nt]);
        }

        if (j0 + 63 > q0) {
            #pragma unroll
            for (int nt = 0; nt < 8; ++nt) {
                int c = j0 + nt * 8 + qd * 2;
                if (c > grow0)     sacc[nt][0] = -1e30f;
                if (c + 1 > grow0) sacc[nt][1] = -1e30f;
                if (c > grow1)     sacc[nt][2] = -1e30f;
                if (c + 1 > grow1) sacc[nt][3] = -1e30f;
            }
        }

        float rm0 = -1e30f, rm1 = -1e30f;
        #pragma unroll
        for (int nt = 0; nt < 8; ++nt) {
            rm0 = fmaxf(rm0, fmaxf(sacc[nt][0], sacc[nt][1]));
            rm1 = fmaxf(rm1, fmaxf(sacc[nt][2], sacc[nt][3]));
        }
        rm0 = fmaxf(rm0, __shfl_xor_sync(0xffffffffu, rm0, 1));
        rm0 = fmaxf(rm0, __shfl_xor_sync(0xffffffffu, rm0, 2));
        rm1 = fmaxf(rm1, __shfl_xor_sync(0xffffffffu, rm1, 1));
        rm1 = fmaxf(rm1, __shfl_xor_sync(0xffffffffu, rm1, 2));

        float mn0 = fmaxf(m0r, rm0);
        float mn1 = fmaxf(m1r, rm1);
        float corr0 = __expf(m0r - mn0);
        float corr1 = __expf(m1r - mn1);
        m0r = mn0; m1r = mn1;

        float rs0 = 0.0f, rs1 = 0.0f;
        #pragma unroll
        for (int nt = 0; nt < 8; ++nt) {
            float p0 = __expf(sacc[nt][0] - mn0);
            float p1 = __expf(sacc[nt][1] - mn0);
            float p2 = __expf(sacc[nt][2] - mn1);
            float p3 = __expf(sacc[nt][3] - mn1);
            rs0 += p0 + p1;
            rs1 += p2 + p3;
            sP[r0 * FPW + nt * 4 + qd] = pack_h2(p0, p1);
            sP[(r0 + 8) * FPW + nt * 4 + qd] = pack_h2(p2, p3);
        }
        rs0 += __shfl_xor_sync(0xffffffffu, rs0, 1);
        rs0 += __shfl_xor_sync(0xffffffffu, rs0, 2);
        rs1 += __shfl_xor_sync(0xffffffffu, rs1, 1);
        rs1 += __shfl_xor_sync(0xffffffffu, rs1, 2);
        l0r = l0r * corr0 + rs0;
        l1r = l1r * corr1 + rs1;

        #pragma unroll
        for (int nt = 0; nt < 8; ++nt) {
            o[nt][0] *= corr0;
            o[nt][1] *= corr0;
            o[nt][2] *= corr1;
            o[nt][3] *= corr1;
        }
        __syncwarp();

        #pragma unroll
        for (int ks = 0; ks < 4; ++ks) {
            uint32_t af[4];
            af[0] = sP[r0 * FPW + ks * 8 + qd];
            af[1] = sP[(r0 + 8) * FPW + ks * 8 + qd];
            af[2] = sP[r0 * FPW + ks * 8 + qd + 4];
            af[3] = sP[(r0 + 8) * FPW + ks * 8 + qd + 4];
            #pragma unroll
            for (int nt = 0; nt < 8; ++nt) {
                uint32_t bf[2];
                bf[0] = sV[(nt * 8 + grp) * FPW + ks * 8 + qd];
                bf[1] = sV[(nt * 8 + grp) * FPW + ks * 8 + qd + 4];
                mma_f16_16n8k16(o[nt], af, bf);
            }
        }

        __syncthreads();
        if (t + 2 < ntiles) produce(t + 2);
    }

    // epilogue: z fp16 [b,s,h,a]
    const int b = bh >> 4;
    const int h = bh & 15;
    const float inv0 = 1.0f / l0r;
    const float inv1 = 1.0f / l1r;
    #pragma unroll
    for (int nt = 0; nt < 8; ++nt) {
        const int a = nt * 8 + qd * 2;
        *(uint32_t*)&g_zh[(((size_t)b * Sn + grow0) * Hn + h) * An + a] =
            pack_h2(o[nt][0] * inv0, o[nt][1] * inv0);
        *(uint32_t*)&g_zh[(((size_t)b * Sn + grow1) * Hn + h) * An + a] =
            pack_h2(o[nt][2] * inv1, o[nt][3] * inv1);
    }
}

// ---------------------------------------------------------------------------
extern "C" void kernel_launch(void* const* d_in, const int* in_sizes, int n_in,
                              void* d_out, int out_size)
{
    const float* residual = (const float*)d_in[0];
    const float* Wq = (const float*)d_in[1];
    const float* Wk = (const float*)d_in[2];
    const float* Wv = (const float*)d_in[3];
    const float* Wo = (const float*)d_in[4];
    const float* bq = (const float*)d_in[5];
    const float* bk = (const float*)d_in[6];
    const float* bv = (const float*)d_in[7];
    const float* bo = (const float*)d_in[8];
    float* out = (float*)d_out;

    cudaFuncSetAttribute(flash_mma_kernel, cudaFuncAttributeMaxDynamicSharedMemorySize,
                         FLASH_SMEM_BYTES);
    cudaFuncSetAttribute(gemm_mma_kernel<0>, cudaFuncAttributeMaxDynamicSharedMemorySize,
                         GEMM_SMEM);
    cudaFuncSetAttribute(gemm_mma_kernel<1>, cudaFuncAttributeMaxDynamicSharedMemorySize,
                         GEMM_SMEM);

    // 0) fp16 prepass: convert + transpose weights
    conv_resid_kernel<<<1024, 256>>>(residual);
    transpose_qkv_kernel<<<dim3(1024 / 32, 64 / 32, 48), dim3(32, 8)>>>(Wq, Wk, Wv);
    transpose_wo_kernel<<<dim3(32, 32), dim3(32, 8)>>>(Wo);

    // 1) QKV projections (fp16 m16n8k16)
    gemm_mma_kernel<0><<<dim3(HA / 128, Mrows / 128, 3), 128, GEMM_SMEM>>>(
        bq, bk, bv, nullptr);

    // 2) Causal flash attention (fp16, double-buffered K/V)
    flash_mma_kernel<<<dim3(Sn / 128, Bn * Hn), 256, FLASH_SMEM_BYTES>>>();

    // 3) Output projection
    gemm_mma_kernel<1><<<dim3(Dn / 128, Mrows / 128, 1), 128, GEMM_SMEM>>>(
        bo, nullptr, nullptr, out);
}

// round 10
// speedup vs baseline: 2.0156x; 1.0891x over previous
#include <cuda_runtime.h>
#include <cuda_fp16.h>
#include <cstdint>

// Problem dims (fixed)
constexpr int Bn = 2;
constexpr int Sn = 2048;
constexpr int Dn = 1024;
constexpr int Hn = 16;
constexpr int An = 64;
constexpr int Mrows = Bn * Sn;        // 4096
constexpr int HA = Hn * An;           // 1024

// Scratch (device globals; allocation-free), fp16 operands
__device__ __align__(256) __half g_qh[(size_t)Bn * Hn * Sn * An];  // [b,h,s,a], pre-scaled 1/8
__device__ __align__(256) __half g_kh[(size_t)Bn * Hn * Sn * An];  // [b,h,s,a]
__device__ __align__(256) __half g_vh[(size_t)Bn * Hn * Sn * An];  // [b,h,a,s]  (transposed)
__device__ __align__(256) __half g_zh[(size_t)Bn * Sn * Hn * An];  // [b,s,h,a]
__device__ __align__(256) __half g_ath[(size_t)Mrows * Dn];        // residual fp16 [m][k]
__device__ __align__(256) __half g_wh[(size_t)4 * 1024 * 1024];    // weights fp16 [n][k]

// ---------------------------------------------------------------------------
// Helpers
// ---------------------------------------------------------------------------
__device__ __forceinline__ void cp_async16(uint32_t dst, const void* src) {
    asm volatile("cp.async.cg.shared.global [%0], [%1], 16;" :: "r"(dst), "l"(src) : "memory");
}
__device__ __forceinline__ uint32_t smem_u32(const void* p) {
    uint32_t a;
    asm("{ .reg .u64 t; cvta.to.shared.u64 t, %1; cvt.u32.u64 %0, t; }" : "=r"(a) : "l"(p));
    return a;
}
__device__ __forceinline__ void cp_commit() {
    asm volatile("cp.async.commit_group;" ::: "memory");
}
template <int N>
__device__ __forceinline__ void cp_wait() {
    asm volatile("cp.async.wait_group %0;" :: "n"(N) : "memory");
}
__device__ __forceinline__ void mma_f16_16n8k16(float* c, const uint32_t* a, const uint32_t* b) {
    asm volatile(
        "mma.sync.aligned.m16n8k16.row.col.f32.f16.f16.f32 "
        "{%0,%1,%2,%3}, {%4,%5,%6,%7}, {%8,%9}, {%0,%1,%2,%3};"
        : "+f"(c[0]), "+f"(c[1]), "+f"(c[2]), "+f"(c[3])
        : "r"(a[0]), "r"(a[1]), "r"(a[2]), "r"(a[3]), "r"(b[0]), "r"(b[1]));
}
__device__ __forceinline__ void ldsm_x4(uint32_t& r0, uint32_t& r1, uint32_t& r2, uint32_t& r3,
                                        uint32_t addr) {
    asm volatile("ldmatrix.sync.aligned.m8n8.x4.shared.b16 {%0,%1,%2,%3}, [%4];"
                 : "=r"(r0), "=r"(r1), "=r"(r2), "=r"(r3) : "r"(addr));
}
__device__ __forceinline__ uint32_t pack_h2(float x, float y) {
    __half2 h = __floats2half2_rn(x, y);
    return *(uint32_t*)&h;
}

// ---------------------------------------------------------------------------
// Prepass kernels (unchanged from R9)
// ---------------------------------------------------------------------------
__global__ __launch_bounds__(256) void conv_resid_kernel(const float* __restrict__ src)
{
    constexpr int N4 = Mrows * Dn / 4;
    int idx = blockIdx.x * 256 + threadIdx.x;
    int stride = gridDim.x * 256;
    for (int i = idx; i < N4; i += stride) {
        float4 v = ((const float4*)src)[i];
        uint2 o;
        o.x = pack_h2(v.x, v.y);
        o.y = pack_h2(v.z, v.w);
        ((uint2*)g_ath)[i] = o;
    }
}

__global__ void transpose_qkv_kernel(const float* __restrict__ Wq,
                                     const float* __restrict__ Wk,
                                     const float* __restrict__ Wv)
{
    __shared__ float t[32][33];
    const int w = blockIdx.z / 16;
    const int h = blockIdx.z % 16;
    const float* S = (w == 0) ? Wq : (w == 1) ? Wk : Wv;
    S += (size_t)h * Dn * An;
    __half* D = g_wh + (size_t)w * (1024 * 1024) + (size_t)h * 64 * 1024;
    const int d0 = blockIdx.x * 32;
    const int a0 = blockIdx.y * 32;
    #pragma unroll
    for (int i = 0; i < 4; ++i)
        t[threadIdx.y + i * 8][threadIdx.x] = S[(size_t)(d0 + threadIdx.y + i * 8) * An + a0 + threadIdx.x];
    __syncthreads();
    #pragma unroll
    for (int i = 0; i < 4; ++i)
        D[(size_t)(a0 + threadIdx.y + i * 8) * 1024 + d0 + threadIdx.x] =
            __float2half_rn(t[threadIdx.x][threadIdx.y + i * 8]);
}

__global__ void transpose_wo_kernel(const float* __restrict__ Wo)
{
    __shared__ float t[32][33];
    __half* D = g_wh + (size_t)3 * (1024 * 1024);
    const int k0 = blockIdx.x * 32;
    const int n0 = blockIdx.y * 32;
    #pragma unroll
    for (int i = 0; i < 4; ++i)
        t[threadIdx.y + i * 8][threadIdx.x] = Wo[(size_t)(k0 + threadIdx.y + i * 8) * Dn + n0 + threadIdx.x];
    __syncthreads();
    #pragma unroll
    for (int i = 0; i < 4; ++i)
        D[(size_t)(n0 + threadIdx.y + i * 8) * 1024 + k0 + threadIdx.x] =
            __float2half_rn(t[threadIdx.x][threadIdx.y + i * 8]);
}

// ---------------------------------------------------------------------------
// fp16 GEMM: BM=128 BN=128 BK=64, 128 threads (2m x 2n warps, 64x64 tiles),
// 3-stage cp.async, ldmatrix fragment loads. Pitch 144 B (LDSM conflict-free).
// ---------------------------------------------------------------------------
constexpr int GP = 144;                       // row pitch bytes
constexpr int A_STG_B = 128 * GP;             // 18432
constexpr int STG_B = 2 * A_STG_B;            // 36864
constexpr int NSTAGE = 3;
constexpr int GEMM_SMEM = NSTAGE * STG_B;     // 110592
constexpr int KCHUNKS = 1024 / 64;            // 16

template<int MODE>
__global__ __launch_bounds__(128) void gemm_mma_kernel(
    const float* __restrict__ b0, const float* __restrict__ b1, const float* __restrict__ b2,
    float* __restrict__ outp)
{
    extern __shared__ __align__(16) uint32_t smem[];

    const int tid = threadIdx.x;
    const int lane = tid & 31;
    const int wid = tid >> 5;
    const int warp_m = wid & 1;
    const int warp_n = wid >> 1;
    const int grp = lane >> 2;
    const int qd = lane & 3;

    const int m0 = blockIdx.y * 128;
    const int n0 = blockIdx.x * 128;
    const int z = blockIdx.z;

    const __half* A = (MODE == 0) ? g_ath : g_zh;
    const __half* W = (MODE == 0) ? (g_wh + (size_t)z * (1024 * 1024))
                                  : (g_wh + (size_t)3 * (1024 * 1024));
    const float* bias = (MODE == 0) ? ((z == 0) ? b0 : (z == 1) ? b1 : b2) : b0;

    const uint32_t smem_base = smem_u32(smem);

    // ldmatrix lane offsets (bytes within a stage)
    const uint32_t offA = (uint32_t)(warp_m * 64 + (lane & 15)) * GP + (uint32_t)(lane >> 4) * 16;
    const uint32_t offB = (uint32_t)(warp_n * 64 + ((lane >> 4) & 1) * 8 + (lane & 7)) * GP
                        + (uint32_t)((lane >> 3) & 1) * 16;

    auto produce = [&](int kc) {
        const int slot = kc % NSTAGE;
        const uint32_t sA = smem_base + (uint32_t)(slot * STG_B);
        const uint32_t sB = sA + (uint32_t)A_STG_B;
        #pragma unroll
        for (int i = 0; i < 8; ++i) {                 // A: 1024 16B segs
            int task = i * 128 + tid;
            int r = task >> 3;
            int seg = task & 7;
            cp_async16(sA + (uint32_t)(r * GP + seg * 16),
                       A + (size_t)(m0 + r) * 1024 + kc * 64 + seg * 8);
        }
        #pragma unroll
        for (int i = 0; i < 8; ++i) {                 // B: 1024 16B segs
            int task = i * 128 + tid;
            int n = task >> 3;
            int seg = task & 7;
            cp_async16(sB + (uint32_t)(n * GP + seg * 16),
                       W + (size_t)(n0 + n) * 1024 + kc * 64 + seg * 8);
        }
        cp_commit();
    };

    float acc[4][8][4];
    #pragma unroll
    for (int mt = 0; mt < 4; ++mt)
        #pragma unroll
        for (int nt = 0; nt < 8; ++nt)
            #pragma unroll
            for (int e = 0; e < 4; ++e) acc[mt][nt][e] = 0.0f;

    produce(0);
    produce(1);

    for (int kc = 0; kc < KCHUNKS; ++kc) {
        cp_wait<1>();
        __syncthreads();
        if (kc + 2 < KCHUNKS) produce(kc + 2);

        const uint32_t sA = smem_base + (uint32_t)((kc % NSTAGE) * STG_B);
        const uint32_t sB = sA + (uint32_t)A_STG_B;

        #pragma unroll
        for (int ks = 0; ks < 4; ++ks) {              // 4 x k16 per 64-chunk
            uint32_t af[4][4], bf[8][2];
            #pragma unroll
            for (int mt = 0; mt < 4; ++mt)
                ldsm_x4(af[mt][0], af[mt][1], af[mt][2], af[mt][3],
                        sA + offA + (uint32_t)(mt * 16 * GP + ks * 32));
            #pragma unroll
            for (int ntp = 0; ntp < 4; ++ntp) {
                uint32_t t0, t1, t2, t3;
                ldsm_x4(t0, t1, t2, t3, sB + offB + (uint32_t)(ntp * 16 * GP + ks * 32));
                bf[2 * ntp][0] = t0; bf[2 * ntp][1] = t1;
                bf[2 * ntp + 1][0] = t2; bf[2 * ntp + 1][1] = t3;
            }
            #pragma unroll
            for (int mt = 0; mt < 4; ++mt)
                #pragma unroll
                for (int nt = 0; nt < 8; ++nt)
                    mma_f16_16n8k16(acc[mt][nt], af[mt], bf[nt]);
        }
    }

    #pragma unroll
    for (int mt = 0; mt < 4; ++mt) {
        #pragma unroll
        for (int half = 0; half < 2; ++half) {
            const int m = m0 + warp_m * 64 + mt * 16 + grp + half * 8;
            #pragma unroll
            for (int nt = 0; nt < 8; ++nt) {
                const int n = n0 + warp_n * 64 + nt * 8 + qd * 2;
                float vx = acc[mt][nt][half * 2 + 0] + bias[n];
                float vy = acc[mt][nt][half * 2 + 1] + bias[n + 1];
                if (MODE == 0) {
                    const int b = m >> 11;
                    const int s = m & 2047;
                    const int h = n >> 6;
                    const int a = n & 63;
                    if (z == 0) {
                        vx *= 0.125f; vy *= 0.125f;
                        *(uint32_t*)&g_qh[(((size_t)b * Hn + h) * Sn + s) * An + a] = pack_h2(vx, vy);
                    } else if (z == 1) {
                        *(uint32_t*)&g_kh[(((size_t)b * Hn + h) * Sn + s) * An + a] = pack_h2(vx, vy);
                    } else {
                        __half* Vd = g_vh + (((size_t)b * Hn + h) * An) * Sn;
                        Vd[(size_t)a * Sn + s] = __float2half_rn(vx);
                        Vd[(size_t)(a + 1) * Sn + s] = __float2half_rn(vy);
                    }
                } else {
                    float2 v2 = {vx, vy};
                    *(float2*)&outp[(size_t)m * Dn + n] = v2;
                }
            }
        }
    }
}

// ---------------------------------------------------------------------------
// Causal flash attention, fp16 + ldmatrix, cp.async double-buffered K/V.
// Pitch 144 B; SMEM: 2 KV stages + P = 55296 B.
// ---------------------------------------------------------------------------
constexpr int FPW = 36;
constexpr int K_STG_B = 64 * 144;       // 9216
constexpr int KV_STG_B = 2 * K_STG_B;   // 18432
constexpr int FLASH_SMEM_BYTES = 2 * KV_STG_B + 128 * 144;   // 55296

__global__ __launch_bounds__(256) void flash_mma_kernel()
{
    extern __shared__ uint32_t sm_u[];
    uint32_t* sP = sm_u + (2 * KV_STG_B) / 4;

    const int tid = threadIdx.x;
    const int lane = tid & 31;
    const int wid = tid >> 5;
    const int grp = lane >> 2;
    const int qd = lane & 3;

    const int bh = blockIdx.y;
    const size_t base = (size_t)bh * Sn * An;
    const int q0 = blockIdx.x * 128;
    const uint32_t smem_base = smem_u32(sm_u);
    const uint32_t sP_b = smem_base + 2 * KV_STG_B;

    // ldmatrix lane offsets
    const uint32_t offQ = (uint32_t)(wid * 16 + (lane & 15)) * 144 + (uint32_t)(lane >> 4) * 16;
    const uint32_t offKV = (uint32_t)(((lane >> 4) & 1) * 8 + (lane & 7)) * 144
                         + (uint32_t)((lane >> 3) & 1) * 16;

    auto produce = [&](int t) {
        const uint32_t sK = smem_base + (uint32_t)((t & 1) * KV_STG_B);
        const uint32_t sV = sK + (uint32_t)K_STG_B;
        const int j0 = t * 64;
        #pragma unroll
        for (int i = 0; i < 2; ++i) {
            int idx = i * 256 + tid;
            int r = idx >> 3;
            int seg = idx & 7;
            cp_async16(sK + (uint32_t)(r * 144 + seg * 16),
                       g_kh + base + (size_t)(j0 + r) * An + seg * 8);
        }
        #pragma unroll
        for (int i = 0; i < 2; ++i) {
            int idx = i * 256 + tid;
            int a = idx >> 3;
            int seg = idx & 7;
            cp_async16(sV + (uint32_t)(a * 144 + seg * 16),
                       g_vh + base + (size_t)a * Sn + j0 + seg * 8);
        }
        cp_commit();
    };

    produce(0);

    // Q fill via cp.async into stage-1 alias
    {
        const uint32_t sQb = smem_base + (uint32_t)KV_STG_B;
        #pragma unroll
        for (int i = 0; i < 4; ++i) {
            int idx = i * 256 + tid;
            int r = idx >> 3;
            int seg = idx & 7;
            cp_async16(sQb + (uint32_t)(r * 144 + seg * 16),
                       g_qh + base + (size_t)(q0 + r) * An + seg * 8);
        }
        cp_commit();
    }
    cp_wait<0>();
    __syncthreads();

    uint32_t qf[4][4];
    #pragma unroll
    for (int ks = 0; ks < 4; ++ks)
        ldsm_x4(qf[ks][0], qf[ks][1], qf[ks][2], qf[ks][3],
                smem_base + KV_STG_B + offQ + ks * 32);
    __syncthreads();
    produce(1);

    const int r0 = wid * 16 + grp;
    float m0r = -1e30f, m1r = -1e30f, l0r = 0.0f, l1r = 0.0f;
    float o[8][4];
    #pragma unroll
    for (int nt = 0; nt < 8; ++nt)
        #pragma unroll
        for (int e = 0; e < 4; ++e) o[nt][e] = 0.0f;

    const int grow0 = q0 + r0;
    const int grow1 = grow0 + 8;
    const int ntiles = (q0 + 128) / 64;

    for (int t = 0; t < ntiles; ++t) {
        cp_wait<1>();
        __syncthreads();

        const uint32_t sK_b = smem_base + (uint32_t)((t & 1) * KV_STG_B);
        const uint32_t sV_b = sK_b + (uint32_t)K_STG_B;
        const int j0 = t * 64;

        float sacc[8][4];
        #pragma unroll
        for (int nt = 0; nt < 8; ++nt)
            #pragma unroll
            for (int e = 0; e < 4; ++e) sacc[nt][e] = 0.0f;

        #pragma unroll
        for (int ks = 0; ks < 4; ++ks) {
            uint32_t kf[8][2];
            #pragma unroll
            for (int ntp = 0; ntp < 4; ++ntp) {
                uint32_t t0, t1, t2, t3;
                ldsm_x4(t0, t1, t2, t3, sK_b + offKV + (uint32_t)(ntp * 16 * 144 + ks * 32));
                kf[2 * ntp][0] = t0; kf[2 * ntp][1] = t1;
                kf[2 * ntp + 1][0] = t2; kf[2 * ntp + 1][1] = t3;
            }
            #pragma unroll
            for (int nt = 0; nt < 8; ++nt)
                mma_f16_16n8k16(sacc[nt], qf[ks], kf[nt]);
        }

        if (j0 + 63 > q0) {
            #pragma unroll
            for (int nt = 0; nt < 8; ++nt) {
                int c = j0 + nt * 8 + qd * 2;
                if (c > grow0)     sacc[nt][0] = -1e30f;
                if (c + 1 > grow0) sacc[nt][1] = -1e30f;
                if (c > grow1)     sacc[nt][2] = -1e30f;
                if (c + 1 > grow1) sacc[nt][3] = -1e30f;
            }
        }

        float rm0 = -1e30f, rm1 = -1e30f;
        #pragma unroll
        for (int nt = 0; nt < 8; ++nt) {
            rm0 = fmaxf(rm0, fmaxf(sacc[nt][0], sacc[nt][1]));
            rm1 = fmaxf(rm1, fmaxf(sacc[nt][2], sacc[nt][3]));
        }
        rm0 = fmaxf(rm0, __shfl_xor_sync(0xffffffffu, rm0, 1));
        rm0 = fmaxf(rm0, __shfl_xor_sync(0xffffffffu, rm0, 2));
        rm1 = fmaxf(rm1, __shfl_xor_sync(0xffffffffu, rm1, 1));
        rm1 = fmaxf(rm1, __shfl_xor_sync(0xffffffffu, rm1, 2));

        float mn0 = fmaxf(m0r, rm0);
        float mn1 = fmaxf(m1r, rm1);
        float corr0 = __expf(m0r - mn0);
        float corr1 = __expf(m1r - mn1);
        m0r = mn0; m1r = mn1;

        float rs0 = 0.0f, rs1 = 0.0f;
        #pragma unroll
        for (int nt = 0; nt < 8; ++nt) {
            float p0 = __expf(sacc[nt][0] - mn0);
            float p1 = __expf(sacc[nt][1] - mn0);
            float p2 = __expf(sacc[nt][2] - mn1);
            float p3 = __expf(sacc[nt][3] - mn1);
            rs0 += p0 + p1;
            rs1 += p2 + p3;
            sP[r0 * FPW + nt * 4 + qd] = pack_h2(p0, p1);
            sP[(r0 + 8) * FPW + nt * 4 + qd] = pack_h2(p2, p3);
        }
        rs0 += __shfl_xor_sync(0xffffffffu, rs0, 1);
        rs0 += __shfl_xor_sync(0xffffffffu, rs0, 2);
        rs1 += __shfl_xor_sync(0xffffffffu, rs1, 1);
        rs1 += __shfl_xor_sync(0xffffffffu, rs1, 2);
        l0r = l0r * corr0 + rs0;
        l1r = l1r * corr1 + rs1;

        #pragma unroll
        for (int nt = 0; nt < 8; ++nt) {
            o[nt][0] *= corr0;
            o[nt][1] *= corr0;
            o[nt][2] *= corr1;
            o[nt][3] *= corr1;
        }
        __syncwarp();

        #pragma unroll
        for (int ks = 0; ks < 4; ++ks) {
            uint32_t af[4];
            ldsm_x4(af[0], af[1], af[2], af[3], sP_b + offQ + ks * 32);
            uint32_t vf[8][2];
            #pragma unroll
            for (int ntp = 0; ntp < 4; ++ntp) {
                uint32_t t0, t1, t2, t3;
                ldsm_x4(t0, t1, t2, t3, sV_b + offKV + (uint32_t)(ntp * 16 * 144 + ks * 32));
                vf[2 * ntp][0] = t0; vf[2 * ntp][1] = t1;
                vf[2 * ntp + 1][0] = t2; vf[2 * ntp + 1][1] = t3;
            }
            #pragma unroll
            for (int nt = 0; nt < 8; ++nt)
                mma_f16_16n8k16(o[nt], af, vf[nt]);
        }

        __syncthreads();
        if (t + 2 < ntiles) produce(t + 2);
    }

    // epilogue: z fp16 [b,s,h,a]
    const int b = bh >> 4;
    const int h = bh & 15;
    const float inv0 = 1.0f / l0r;
    const float inv1 = 1.0f / l1r;
    #pragma unroll
    for (int nt = 0; nt < 8; ++nt) {
        const int a = nt * 8 + qd * 2;
        *(uint32_t*)&g_zh[(((size_t)b * Sn + grow0) * Hn + h) * An + a] =
            pack_h2(o[nt][0] * inv0, o[nt][1] * inv0);
        *(uint32_t*)&g_zh[(((size_t)b * Sn + grow1) * Hn + h) * An + a] =
            pack_h2(o[nt][2] * inv1, o[nt][3] * inv1);
    }
}

// ---------------------------------------------------------------------------
extern "C" void kernel_launch(void* const* d_in, const int* in_sizes, int n_in,
                              void* d_out, int out_size)
{
    const float* residual = (const float*)d_in[0];
    const float* Wq = (const float*)d_in[1];
    const float* Wk = (const float*)d_in[2];
    const float* Wv = (const float*)d_in[3];
    const float* Wo = (const float*)d_in[4];
    const float* bq = (const float*)d_in[5];
    const float* bk = (const float*)d_in[6];
    const float* bv = (const float*)d_in[7];
    const float* bo = (const float*)d_in[8];
    float* out = (float*)d_out;

    cudaFuncSetAttribute(flash_mma_kernel, cudaFuncAttributeMaxDynamicSharedMemorySize,
                         FLASH_SMEM_BYTES);
    cudaFuncSetAttribute(gemm_mma_kernel<0>, cudaFuncAttributeMaxDynamicSharedMemorySize,
                         GEMM_SMEM);
    cudaFuncSetAttribute(gemm_mma_kernel<1>, cudaFuncAttributeMaxDynamicSharedMemorySize,
                         GEMM_SMEM);

    // 0) fp16 prepass
    conv_resid_kernel<<<1024, 256>>>(residual);
    transpose_qkv_kernel<<<dim3(1024 / 32, 64 / 32, 48), dim3(32, 8)>>>(Wq, Wk, Wv);
    transpose_wo_kernel<<<dim3(32, 32), dim3(32, 8)>>>(Wo);

    // 1) QKV projections (fp16 + ldmatrix, BK=64)
    gemm_mma_kernel<0><<<dim3(HA / 128, Mrows / 128, 3), 128, GEMM_SMEM>>>(
        bq, bk, bv, nullptr);

    // 2) Causal flash attention (fp16 + ldmatrix)
    flash_mma_kernel<<<dim3(Sn / 128, Bn * Hn), 256, FLASH_SMEM_BYTES>>>();

    // 3) Output projection
    gemm_mma_kernel<1><<<dim3(Dn / 128, Mrows / 128, 1), 128, GEMM_SMEM>>>(
        bo, nullptr, nullptr, out);
}

// round 11
// speedup vs baseline: 2.1202x; 1.0519x over previous
#include <cuda_runtime.h>
#include <cuda_fp16.h>
#include <cstdint>

// Problem dims (fixed)
constexpr int Bn = 2;
constexpr int Sn = 2048;
constexpr int Dn = 1024;
constexpr int Hn = 16;
constexpr int An = 64;
constexpr int Mrows = Bn * Sn;        // 4096
constexpr int HA = Hn * An;           // 1024

// Scratch (device globals; allocation-free), fp16 operands
__device__ __align__(256) __half g_qh[(size_t)Bn * Hn * Sn * An];  // [b,h,s,a], pre-scaled 1/8
__device__ __align__(256) __half g_kh[(size_t)Bn * Hn * Sn * An];  // [b,h,s,a]
__device__ __align__(256) __half g_vh[(size_t)Bn * Hn * Sn * An];  // [b,h,a,s]  (transposed)
__device__ __align__(256) __half g_zh[(size_t)Bn * Sn * Hn * An];  // [b,s,h,a]
__device__ __align__(256) __half g_ath[(size_t)Mrows * Dn];        // residual fp16 [m][k]
__device__ __align__(256) __half g_wh[(size_t)4 * 1024 * 1024];    // weights fp16 [n][k]

// ---------------------------------------------------------------------------
// Helpers
// ---------------------------------------------------------------------------
__device__ __forceinline__ void cp_async16(uint32_t dst, const void* src) {
    asm volatile("cp.async.cg.shared.global [%0], [%1], 16;" :: "r"(dst), "l"(src) : "memory");
}
__device__ __forceinline__ uint32_t smem_u32(const void* p) {
    uint32_t a;
    asm("{ .reg .u64 t; cvta.to.shared.u64 t, %1; cvt.u32.u64 %0, t; }" : "=r"(a) : "l"(p));
    return a;
}
__device__ __forceinline__ void cp_commit() {
    asm volatile("cp.async.commit_group;" ::: "memory");
}
template <int N>
__device__ __forceinline__ void cp_wait() {
    asm volatile("cp.async.wait_group %0;" :: "n"(N) : "memory");
}
__device__ __forceinline__ void mma_f16_16n8k16(float* c, const uint32_t* a, const uint32_t* b) {
    asm volatile(
        "mma.sync.aligned.m16n8k16.row.col.f32.f16.f16.f32 "
        "{%0,%1,%2,%3}, {%4,%5,%6,%7}, {%8,%9}, {%0,%1,%2,%3};"
        : "+f"(c[0]), "+f"(c[1]), "+f"(c[2]), "+f"(c[3])
        : "r"(a[0]), "r"(a[1]), "r"(a[2]), "r"(a[3]), "r"(b[0]), "r"(b[1]));
}
__device__ __forceinline__ void ldsm_x4(uint32_t& r0, uint32_t& r1, uint32_t& r2, uint32_t& r3,
                                        uint32_t addr) {
    asm volatile("ldmatrix.sync.aligned.m8n8.x4.shared.b16 {%0,%1,%2,%3}, [%4];"
                 : "=r"(r0), "=r"(r1), "=r"(r2), "=r"(r3) : "r"(addr));
}
__device__ __forceinline__ uint32_t pack_h2(float x, float y) {
    __half2 h = __floats2half2_rn(x, y);
    return *(uint32_t*)&h;
}

// ---------------------------------------------------------------------------
// Prepass kernels (unchanged)
// ---------------------------------------------------------------------------
__global__ __launch_bounds__(256) void conv_resid_kernel(const float* __restrict__ src)
{
    constexpr int N4 = Mrows * Dn / 4;
    int idx = blockIdx.x * 256 + threadIdx.x;
    int stride = gridDim.x * 256;
    for (int i = idx; i < N4; i += stride) {
        float4 v = ((const float4*)src)[i];
        uint2 o;
        o.x = pack_h2(v.x, v.y);
        o.y = pack_h2(v.z, v.w);
        ((uint2*)g_ath)[i] = o;
    }
}

__global__ void transpose_qkv_kernel(const float* __restrict__ Wq,
                                     const float* __restrict__ Wk,
                                     const float* __restrict__ Wv)
{
    __shared__ float t[32][33];
    const int w = blockIdx.z / 16;
    const int h = blockIdx.z % 16;
    const float* S = (w == 0) ? Wq : (w == 1) ? Wk : Wv;
    S += (size_t)h * Dn * An;
    __half* D = g_wh + (size_t)w * (1024 * 1024) + (size_t)h * 64 * 1024;
    const int d0 = blockIdx.x * 32;
    const int a0 = blockIdx.y * 32;
    #pragma unroll
    for (int i = 0; i < 4; ++i)
        t[threadIdx.y + i * 8][threadIdx.x] = S[(size_t)(d0 + threadIdx.y + i * 8) * An + a0 + threadIdx.x];
    __syncthreads();
    #pragma unroll
    for (int i = 0; i < 4; ++i)
        D[(size_t)(a0 + threadIdx.y + i * 8) * 1024 + d0 + threadIdx.x] =
            __float2half_rn(t[threadIdx.x][threadIdx.y + i * 8]);
}

__global__ void transpose_wo_kernel(const float* __restrict__ Wo)
{
    __shared__ float t[32][33];
    __half* D = g_wh + (size_t)3 * (1024 * 1024);
    const int k0 = blockIdx.x * 32;
    const int n0 = blockIdx.y * 32;
    #pragma unroll
    for (int i = 0; i < 4; ++i)
        t[threadIdx.y + i * 8][threadIdx.x] = Wo[(size_t)(k0 + threadIdx.y + i * 8) * Dn + n0 + threadIdx.x];
    __syncthreads();
    #pragma unroll
    for (int i = 0; i < 4; ++i)
        D[(size_t)(n0 + threadIdx.y + i * 8) * 1024 + k0 + threadIdx.x] =
            __float2half_rn(t[threadIdx.x][threadIdx.y + i * 8]);
}

// ---------------------------------------------------------------------------
// fp16 GEMM: BM=128 BN=128 BK=64, 128 threads, ldmatrix, NSTAGE=2 (72 KB
// SMEM -> 3 CTAs/SM). Produce-after-consume ring (2-slot safe).
// ---------------------------------------------------------------------------
constexpr int GP = 144;                       // row pitch bytes
constexpr int A_STG_B = 128 * GP;             // 18432
constexpr int STG_B = 2 * A_STG_B;            // 36864
constexpr int NSTAGE = 2;
constexpr int GEMM_SMEM = NSTAGE * STG_B;     // 73728
constexpr int KCHUNKS = 1024 / 64;            // 16

template<int MODE>
__global__ __launch_bounds__(128, 3) void gemm_mma_kernel(
    const float* __restrict__ b0, const float* __restrict__ b1, const float* __restrict__ b2,
    float* __restrict__ outp)
{
    extern __shared__ __align__(16) uint32_t smem[];

    const int tid = threadIdx.x;
    const int lane = tid & 31;
    const int wid = tid >> 5;
    const int warp_m = wid & 1;
    const int warp_n = wid >> 1;
    const int grp = lane >> 2;
    const int qd = lane & 3;

    const int m0 = blockIdx.y * 128;
    const int n0 = blockIdx.x * 128;
    const int z = blockIdx.z;

    const __half* A = (MODE == 0) ? g_ath : g_zh;
    const __half* W = (MODE == 0) ? (g_wh + (size_t)z * (1024 * 1024))
                                  : (g_wh + (size_t)3 * (1024 * 1024));
    const float* bias = (MODE == 0) ? ((z == 0) ? b0 : (z == 1) ? b1 : b2) : b0;

    const uint32_t smem_base = smem_u32(smem);

    const uint32_t offA = (uint32_t)(warp_m * 64 + (lane & 15)) * GP + (uint32_t)(lane >> 4) * 16;
    const uint32_t offB = (uint32_t)(warp_n * 64 + ((lane >> 4) & 1) * 8 + (lane & 7)) * GP
                        + (uint32_t)((lane >> 3) & 1) * 16;

    auto produce = [&](int kc) {
        const int slot = kc & 1;
        const uint32_t sA = smem_base + (uint32_t)(slot * STG_B);
        const uint32_t sB = sA + (uint32_t)A_STG_B;
        #pragma unroll
        for (int i = 0; i < 8; ++i) {
            int task = i * 128 + tid;
            int r = task >> 3;
            int seg = task & 7;
            cp_async16(sA + (uint32_t)(r * GP + seg * 16),
                       A + (size_t)(m0 + r) * 1024 + kc * 64 + seg * 8);
        }
        #pragma unroll
        for (int i = 0; i < 8; ++i) {
            int task = i * 128 + tid;
            int n = task >> 3;
            int seg = task & 7;
            cp_async16(sB + (uint32_t)(n * GP + seg * 16),
                       W + (size_t)(n0 + n) * 1024 + kc * 64 + seg * 8);
        }
        cp_commit();
    };

    float acc[4][8][4];
    #pragma unroll
    for (int mt = 0; mt < 4; ++mt)
        #pragma unroll
        for (int nt = 0; nt < 8; ++nt)
            #pragma unroll
            for (int e = 0; e < 4; ++e) acc[mt][nt][e] = 0.0f;

    produce(0);
    produce(1);

    for (int kc = 0; kc < KCHUNKS; ++kc) {
        cp_wait<1>();
        __syncthreads();

        const uint32_t sA = smem_base + (uint32_t)((kc & 1) * STG_B);
        const uint32_t sB = sA + (uint32_t)A_STG_B;

        #pragma unroll
        for (int ks = 0; ks < 4; ++ks) {
            uint32_t af[4][4], bf[8][2];
            #pragma unroll
            for (int mt = 0; mt < 4; ++mt)
                ldsm_x4(af[mt][0], af[mt][1], af[mt][2], af[mt][3],
                        sA + offA + (uint32_t)(mt * 16 * GP + ks * 32));
            #pragma unroll
            for (int ntp = 0; ntp < 4; ++ntp) {
                uint32_t t0, t1, t2, t3;
                ldsm_x4(t0, t1, t2, t3, sB + offB + (uint32_t)(ntp * 16 * GP + ks * 32));
                bf[2 * ntp][0] = t0; bf[2 * ntp][1] = t1;
                bf[2 * ntp + 1][0] = t2; bf[2 * ntp + 1][1] = t3;
            }
            #pragma unroll
            for (int mt = 0; mt < 4; ++mt)
                #pragma unroll
                for (int nt = 0; nt < 8; ++nt)
                    mma_f16_16n8k16(acc[mt][nt], af[mt], bf[nt]);
        }

        __syncthreads();                       // all reads of slot kc&1 done
        if (kc + 2 < KCHUNKS) produce(kc + 2); // overwrites slot kc&1
    }

    #pragma unroll
    for (int mt = 0; mt < 4; ++mt) {
        #pragma unroll
        for (int half = 0; half < 2; ++half) {
            const int m = m0 + warp_m * 64 + mt * 16 + grp + half * 8;
            #pragma unroll
            for (int nt = 0; nt < 8; ++nt) {
                const int n = n0 + warp_n * 64 + nt * 8 + qd * 2;
                float vx = acc[mt][nt][half * 2 + 0] + bias[n];
                float vy = acc[mt][nt][half * 2 + 1] + bias[n + 1];
                if (MODE == 0) {
                    const int b = m >> 11;
                    const int s = m & 2047;
                    const int h = n >> 6;
                    const int a = n & 63;
                    if (z == 0) {
                        vx *= 0.125f; vy *= 0.125f;
                        *(uint32_t*)&g_qh[(((size_t)b * Hn + h) * Sn + s) * An + a] = pack_h2(vx, vy);
                    } else if (z == 1) {
                        *(uint32_t*)&g_kh[(((size_t)b * Hn + h) * Sn + s) * An + a] = pack_h2(vx, vy);
                    } else {
                        __half* Vd = g_vh + (((size_t)b * Hn + h) * An) * Sn;
                        Vd[(size_t)a * Sn + s] = __float2half_rn(vx);
                        Vd[(size_t)(a + 1) * Sn + s] = __float2half_rn(vy);
                    }
                } else {
                    float2 v2 = {vx, vy};
                    *(float2*)&outp[(size_t)m * Dn + n] = v2;
                }
            }
        }
    }
}

// ---------------------------------------------------------------------------
// Causal flash attention (unchanged from R10, proven)
// ---------------------------------------------------------------------------
constexpr int FPW = 36;
constexpr int K_STG_B = 64 * 144;       // 9216
constexpr int KV_STG_B = 2 * K_STG_B;   // 18432
constexpr int FLASH_SMEM_BYTES = 2 * KV_STG_B + 128 * 144;   // 55296

__global__ __launch_bounds__(256) void flash_mma_kernel()
{
    extern __shared__ uint32_t sm_u[];
    uint32_t* sP = sm_u + (2 * KV_STG_B) / 4;

    const int tid = threadIdx.x;
    const int lane = tid & 31;
    const int wid = tid >> 5;
    const int grp = lane >> 2;
    const int qd = lane & 3;

    const int bh = blockIdx.y;
    const size_t base = (size_t)bh * Sn * An;
    const int q0 = blockIdx.x * 128;
    const uint32_t smem_base = smem_u32(sm_u);
    const uint32_t sP_b = smem_base + 2 * KV_STG_B;

    const uint32_t offQ = (uint32_t)(wid * 16 + (lane & 15)) * 144 + (uint32_t)(lane >> 4) * 16;
    const uint32_t offKV = (uint32_t)(((lane >> 4) & 1) * 8 + (lane & 7)) * 144
                         + (uint32_t)((lane >> 3) & 1) * 16;

    auto produce = [&](int t) {
        const uint32_t sK = smem_base + (uint32_t)((t & 1) * KV_STG_B);
        const uint32_t sV = sK + (uint32_t)K_STG_B;
        const int j0 = t * 64;
        #pragma unroll
        for (int i = 0; i < 2; ++i) {
            int idx = i * 256 + tid;
            int r = idx >> 3;
            int seg = idx & 7;
            cp_async16(sK + (uint32_t)(r * 144 + seg * 16),
                       g_kh + base + (size_t)(j0 + r) * An + seg * 8);
        }
        #pragma unroll
        for (int i = 0; i < 2; ++i) {
            int idx = i * 256 + tid;
            int a = idx >> 3;
            int seg = idx & 7;
            cp_async16(sV + (uint32_t)(a * 144 + seg * 16),
                       g_vh + base + (size_t)a * Sn + j0 + seg * 8);
        }
        cp_commit();
    };

    produce(0);

    {
        const uint32_t sQb = smem_base + (uint32_t)KV_STG_B;
        #pragma unroll
        for (int i = 0; i < 4; ++i) {
            int idx = i * 256 + tid;
            int r = idx >> 3;
            int seg = idx & 7;
            cp_async16(sQb + (uint32_t)(r * 144 + seg * 16),
                       g_qh + base + (size_t)(q0 + r) * An + seg * 8);
        }
        cp_commit();
    }
    cp_wait<0>();
    __syncthreads();

    uint32_t qf[4][4];
    #pragma unroll
    for (int ks = 0; ks < 4; ++ks)
        ldsm_x4(qf[ks][0], qf[ks][1], qf[ks][2], qf[ks][3],
                smem_base + KV_STG_B + offQ + ks * 32);
    __syncthreads();
    produce(1);

    const int r0 = wid * 16 + grp;
    float m0r = -1e30f, m1r = -1e30f, l0r = 0.0f, l1r = 0.0f;
    float o[8][4];
    #pragma unroll
    for (int nt = 0; nt < 8; ++nt)
        #pragma unroll
        for (int e = 0; e < 4; ++e) o[nt][e] = 0.0f;

    const int grow0 = q0 + r0;
    const int grow1 = grow0 + 8;
    const int ntiles = (q0 + 128) / 64;

    for (int t = 0; t < ntiles; ++t) {
        cp_wait<1>();
        __syncthreads();

        const uint32_t sK_b = smem_base + (uint32_t)((t & 1) * KV_STG_B);
        const uint32_t sV_b = sK_b + (uint32_t)K_STG_B;
        const int j0 = t * 64;

        float sacc[8][4];
        #pragma unroll
        for (int nt = 0; nt < 8; ++nt)
            #pragma unroll
            for (int e = 0; e < 4; ++e) sacc[nt][e] = 0.0f;

        #pragma unroll
        for (int ks = 0; ks < 4; ++ks) {
            uint32_t kf[8][2];
            #pragma unroll
            for (int ntp = 0; ntp < 4; ++ntp) {
                uint32_t t0, t1, t2, t3;
                ldsm_x4(t0, t1, t2, t3, sK_b + offKV + (uint32_t)(ntp * 16 * 144 + ks * 32));
                kf[2 * ntp][0] = t0; kf[2 * ntp][1] = t1;
                kf[2 * ntp + 1][0] = t2; kf[2 * ntp + 1][1] = t3;
            }
            #pragma unroll
            for (int nt = 0; nt < 8; ++nt)
                mma_f16_16n8k16(sacc[nt], qf[ks], kf[nt]);
        }

        if (j0 + 63 > q0) {
            #pragma unroll
            for (int nt = 0; nt < 8; ++nt) {
                int c = j0 + nt * 8 + qd * 2;
                if (c > grow0)     sacc[nt][0] = -1e30f;
                if (c + 1 > grow0) sacc[nt][1] = -1e30f;
                if (c > grow1)     sacc[nt][2] = -1e30f;
                if (c + 1 > grow1) sacc[nt][3] = -1e30f;
            }
        }

        float rm0 = -1e30f, rm1 = -1e30f;
        #pragma unroll
        for (int nt = 0; nt < 8; ++nt) {
            rm0 = fmaxf(rm0, fmaxf(sacc[nt][0], sacc[nt][1]));
            rm1 = fmaxf(rm1, fmaxf(sacc[nt][2], sacc[nt][3]));
        }
        rm0 = fmaxf(rm0, __shfl_xor_sync(0xffffffffu, rm0, 1));
        rm0 = fmaxf(rm0, __shfl_xor_sync(0xffffffffu, rm0, 2));
        rm1 = fmaxf(rm1, __shfl_xor_sync(0xffffffffu, rm1, 1));
        rm1 = fmaxf(rm1, __shfl_xor_sync(0xffffffffu, rm1, 2));

        float mn0 = fmaxf(m0r, rm0);
        float mn1 = fmaxf(m1r, rm1);
        float corr0 = __expf(m0r - mn0);
        float corr1 = __expf(m1r - mn1);
        m0r = mn0; m1r = mn1;

        float rs0 = 0.0f, rs1 = 0.0f;
        #pragma unroll
        for (int nt = 0; nt < 8; ++nt) {
            float p0 = __expf(sacc[nt][0] - mn0);
            float p1 = __expf(sacc[nt][1] - mn0);
            float p2 = __expf(sacc[nt][2] - mn1);
            float p3 = __expf(sacc[nt][3] - mn1);
            rs0 += p0 + p1;
            rs1 += p2 + p3;
            sP[r0 * FPW + nt * 4 + qd] = pack_h2(p0, p1);
            sP[(r0 + 8) * FPW + nt * 4 + qd] = pack_h2(p2, p3);
        }
        rs0 += __shfl_xor_sync(0xffffffffu, rs0, 1);
        rs0 += __shfl_xor_sync(0xffffffffu, rs0, 2);
        rs1 += __shfl_xor_sync(0xffffffffu, rs1, 1);
        rs1 += __shfl_xor_sync(0xffffffffu, rs1, 2);
        l0r = l0r * corr0 + rs0;
        l1r = l1r * corr1 + rs1;

        #pragma unroll
        for (int nt = 0; nt < 8; ++nt) {
            o[nt][0] *= corr0;
            o[nt][1] *= corr0;
            o[nt][2] *= corr1;
            o[nt][3] *= corr1;
        }
        __syncwarp();

        #pragma unroll
        for (int ks = 0; ks < 4; ++ks) {
            uint32_t af[4];
            ldsm_x4(af[0], af[1], af[2], af[3], sP_b + offQ + ks * 32);
            uint32_t vf[8][2];
            #pragma unroll
            for (int ntp = 0; ntp < 4; ++ntp) {
                uint32_t t0, t1, t2, t3;
                ldsm_x4(t0, t1, t2, t3, sV_b + offKV + (uint32_t)(ntp * 16 * 144 + ks * 32));
                vf[2 * ntp][0] = t0; vf[2 * ntp][1] = t1;
                vf[2 * ntp + 1][0] = t2; vf[2 * ntp + 1][1] = t3;
            }
            #pragma unroll
            for (int nt = 0; nt < 8; ++nt)
                mma_f16_16n8k16(o[nt], af, vf[nt]);
        }

        __syncthreads();
        if (t + 2 < ntiles) produce(t + 2);
    }

    const int b = bh >> 4;
    const int h = bh & 15;
    const float inv0 = 1.0f / l0r;
    const float inv1 = 1.0f / l1r;
    #pragma unroll
    for (int nt = 0; nt < 8; ++nt) {
        const int a = nt * 8 + qd * 2;
        *(uint32_t*)&g_zh[(((size_t)b * Sn + grow0) * Hn + h) * An + a] =
            pack_h2(o[nt][0] * inv0, o[nt][1] * inv0);
        *(uint32_t*)&g_zh[(((size_t)b * Sn + grow1) * Hn + h) * An + a] =
            pack_h2(o[nt][2] * inv1, o[nt][3] * inv1);
    }
}

// ---------------------------------------------------------------------------
extern "C" void kernel_launch(void* const* d_in, const int* in_sizes, int n_in,
                              void* d_out, int out_size)
{
    const float* residual = (const float*)d_in[0];
    const float* Wq = (const float*)d_in[1];
    const float* Wk = (const float*)d_in[2];
    const float* Wv = (const float*)d_in[3];
    const float* Wo = (const float*)d_in[4];
    const float* bq = (const float*)d_in[5];
    const float* bk = (const float*)d_in[6];
    const float* bv = (const float*)d_in[7];
    const float* bo = (const float*)d_in[8];
    float* out = (float*)d_out;

    cudaFuncSetAttribute(flash_mma_kernel, cudaFuncAttributeMaxDynamicSharedMemorySize,
                         FLASH_SMEM_BYTES);
    cudaFuncSetAttribute(gemm_mma_kernel<0>, cudaFuncAttributeMaxDynamicSharedMemorySize,
                         GEMM_SMEM);
    cudaFuncSetAttribute(gemm_mma_kernel<1>, cudaFuncAttributeMaxDynamicSharedMemorySize,
                         GEMM_SMEM);

    // 0) fp16 prepass
    conv_resid_kernel<<<1024, 256>>>(residual);
    transpose_qkv_kernel<<<dim3(1024 / 32, 64 / 32, 48), dim3(32, 8)>>>(Wq, Wk, Wv);
    transpose_wo_kernel<<<dim3(32, 32), dim3(32, 8)>>>(Wo);

    // 1) QKV projections (fp16 + ldmatrix, NSTAGE=2, 3 CTAs/SM)
    gemm_mma_kernel<0><<<dim3(HA / 128, Mrows / 128, 3), 128, GEMM_SMEM>>>(
        bq, bk, bv, nullptr);

    // 2) Causal flash attention (fp16 + ldmatrix)
    flash_mma_kernel<<<dim3(Sn / 128, Bn * Hn), 256, FLASH_SMEM_BYTES>>>();

    // 3) Output projection
    gemm_mma_kernel<1><<<dim3(Dn / 128, Mrows / 128, 1), 128, GEMM_SMEM>>>(
        bo, nullptr, nullptr, out);
}

// round 12
// speedup vs baseline: 2.2192x; 1.0467x over previous
#include <cuda_runtime.h>
#include <cuda_fp16.h>
#include <cstdint>

// Problem dims (fixed)
constexpr int Bn = 2;
constexpr int Sn = 2048;
constexpr int Dn = 1024;
constexpr int Hn = 16;
constexpr int An = 64;
constexpr int Mrows = Bn * Sn;        // 4096
constexpr int HA = Hn * An;           // 1024

// Scratch (device globals; allocation-free), fp16 operands
__device__ __align__(256) __half g_qh[(size_t)Bn * Hn * Sn * An];  // [b,h,s,a], pre-scaled 1/8
__device__ __align__(256) __half g_kh[(size_t)Bn * Hn * Sn * An];  // [b,h,s,a]
__device__ __align__(256) __half g_vh[(size_t)Bn * Hn * Sn * An];  // [b,h,a,s]  (transposed)
__device__ __align__(256) __half g_zh[(size_t)Bn * Sn * Hn * An];  // [b,s,h,a]
__device__ __align__(256) __half g_ath[(size_t)Mrows * Dn];        // residual fp16 [m][k]
__device__ __align__(256) __half g_wh[(size_t)4 * 1024 * 1024];    // weights fp16 [n][k]

// ---------------------------------------------------------------------------
// Helpers
// ---------------------------------------------------------------------------
__device__ __forceinline__ void cp_async16(uint32_t dst, const void* src) {
    asm volatile("cp.async.cg.shared.global [%0], [%1], 16;" :: "r"(dst), "l"(src) : "memory");
}
__device__ __forceinline__ uint32_t smem_u32(const void* p) {
    uint32_t a;
    asm("{ .reg .u64 t; cvta.to.shared.u64 t, %1; cvt.u32.u64 %0, t; }" : "=r"(a) : "l"(p));
    return a;
}
__device__ __forceinline__ void cp_commit() {
    asm volatile("cp.async.commit_group;" ::: "memory");
}
template <int N>
__device__ __forceinline__ void cp_wait() {
    asm volatile("cp.async.wait_group %0;" :: "n"(N) : "memory");
}
__device__ __forceinline__ void mma_f16_16n8k16(float* c, const uint32_t* a, const uint32_t* b) {
    asm volatile(
        "mma.sync.aligned.m16n8k16.row.col.f32.f16.f16.f32 "
        "{%0,%1,%2,%3}, {%4,%5,%6,%7}, {%8,%9}, {%0,%1,%2,%3};"
        : "+f"(c[0]), "+f"(c[1]), "+f"(c[2]), "+f"(c[3])
        : "r"(a[0]), "r"(a[1]), "r"(a[2]), "r"(a[3]), "r"(b[0]), "r"(b[1]));
}
__device__ __forceinline__ void ldsm_x4(uint32_t& r0, uint32_t& r1, uint32_t& r2, uint32_t& r3,
                                        uint32_t addr) {
    asm volatile("ldmatrix.sync.aligned.m8n8.x4.shared.b16 {%0,%1,%2,%3}, [%4];"
                 : "=r"(r0), "=r"(r1), "=r"(r2), "=r"(r3) : "r"(addr));
}
__device__ __forceinline__ uint32_t pack_h2(float x, float y) {
    __half2 h = __floats2half2_rn(x, y);
    return *(uint32_t*)&h;
}

// ---------------------------------------------------------------------------
// Prepass kernels (unchanged)
// ---------------------------------------------------------------------------
__global__ __launch_bounds__(256) void conv_resid_kernel(const float* __restrict__ src)
{
    constexpr int N4 = Mrows * Dn / 4;
    int idx = blockIdx.x * 256 + threadIdx.x;
    int stride = gridDim.x * 256;
    for (int i = idx; i < N4; i += stride) {
        float4 v = ((const float4*)src)[i];
        uint2 o;
        o.x = pack_h2(v.x, v.y);
        o.y = pack_h2(v.z, v.w);
        ((uint2*)g_ath)[i] = o;
    }
}

__global__ void transpose_qkv_kernel(const float* __restrict__ Wq,
                                     const float* __restrict__ Wk,
                                     const float* __restrict__ Wv)
{
    __shared__ float t[32][33];
    const int w = blockIdx.z / 16;
    const int h = blockIdx.z % 16;
    const float* S = (w == 0) ? Wq : (w == 1) ? Wk : Wv;
    S += (size_t)h * Dn * An;
    __half* D = g_wh + (size_t)w * (1024 * 1024) + (size_t)h * 64 * 1024;
    const int d0 = blockIdx.x * 32;
    const int a0 = blockIdx.y * 32;
    #pragma unroll
    for (int i = 0; i < 4; ++i)
        t[threadIdx.y + i * 8][threadIdx.x] = S[(size_t)(d0 + threadIdx.y + i * 8) * An + a0 + threadIdx.x];
    __syncthreads();
    #pragma unroll
    for (int i = 0; i < 4; ++i)
        D[(size_t)(a0 + threadIdx.y + i * 8) * 1024 + d0 + threadIdx.x] =
            __float2half_rn(t[threadIdx.x][threadIdx.y + i * 8]);
}

__global__ void transpose_wo_kernel(const float* __restrict__ Wo)
{
    __shared__ float t[32][33];
    __half* D = g_wh + (size_t)3 * (1024 * 1024);
    const int k0 = blockIdx.x * 32;
    const int n0 = blockIdx.y * 32;
    #pragma unroll
    for (int i = 0; i < 4; ++i)
        t[threadIdx.y + i * 8][threadIdx.x] = Wo[(size_t)(k0 + threadIdx.y + i * 8) * Dn + n0 + threadIdx.x];
    __syncthreads();
    #pragma unroll
    for (int i = 0; i < 4; ++i)
        D[(size_t)(n0 + threadIdx.y + i * 8) * 1024 + k0 + threadIdx.x] =
            __float2half_rn(t[threadIdx.x][threadIdx.y + i * 8]);
}

// ---------------------------------------------------------------------------
// fp16 GEMM (unchanged from R11, proven)
// ---------------------------------------------------------------------------
constexpr int GP = 144;
constexpr int A_STG_B = 128 * GP;
constexpr int STG_B = 2 * A_STG_B;
constexpr int NSTAGE = 2;
constexpr int GEMM_SMEM = NSTAGE * STG_B;     // 73728
constexpr int KCHUNKS = 1024 / 64;

template<int MODE>
__global__ __launch_bounds__(128, 3) void gemm_mma_kernel(
    const float* __restrict__ b0, const float* __restrict__ b1, const float* __restrict__ b2,
    float* __restrict__ outp)
{
    extern __shared__ __align__(16) uint32_t smem[];

    const int tid = threadIdx.x;
    const int lane = tid & 31;
    const int wid = tid >> 5;
    const int warp_m = wid & 1;
    const int warp_n = wid >> 1;
    const int grp = lane >> 2;
    const int qd = lane & 3;

    const int m0 = blockIdx.y * 128;
    const int n0 = blockIdx.x * 128;
    const int z = blockIdx.z;

    const __half* A = (MODE == 0) ? g_ath : g_zh;
    const __half* W = (MODE == 0) ? (g_wh + (size_t)z * (1024 * 1024))
                                  : (g_wh + (size_t)3 * (1024 * 1024));
    const float* bias = (MODE == 0) ? ((z == 0) ? b0 : (z == 1) ? b1 : b2) : b0;

    const uint32_t smem_base = smem_u32(smem);

    const uint32_t offA = (uint32_t)(warp_m * 64 + (lane & 15)) * GP + (uint32_t)(lane >> 4) * 16;
    const uint32_t offB = (uint32_t)(warp_n * 64 + ((lane >> 4) & 1) * 8 + (lane & 7)) * GP
                        + (uint32_t)((lane >> 3) & 1) * 16;

    auto produce = [&](int kc) {
        const int slot = kc & 1;
        const uint32_t sA = smem_base + (uint32_t)(slot * STG_B);
        const uint32_t sB = sA + (uint32_t)A_STG_B;
        #pragma unroll
        for (int i = 0; i < 8; ++i) {
            int task = i * 128 + tid;
            int r = task >> 3;
            int seg = task & 7;
            cp_async16(sA + (uint32_t)(r * GP + seg * 16),
                       A + (size_t)(m0 + r) * 1024 + kc * 64 + seg * 8);
        }
        #pragma unroll
        for (int i = 0; i < 8; ++i) {
            int task = i * 128 + tid;
            int n = task >> 3;
            int seg = task & 7;
            cp_async16(sB + (uint32_t)(n * GP + seg * 16),
                       W + (size_t)(n0 + n) * 1024 + kc * 64 + seg * 8);
        }
        cp_commit();
    };

    float acc[4][8][4];
    #pragma unroll
    for (int mt = 0; mt < 4; ++mt)
        #pragma unroll
        for (int nt = 0; nt < 8; ++nt)
            #pragma unroll
            for (int e = 0; e < 4; ++e) acc[mt][nt][e] = 0.0f;

    produce(0);
    produce(1);

    for (int kc = 0; kc < KCHUNKS; ++kc) {
        cp_wait<1>();
        __syncthreads();

        const uint32_t sA = smem_base + (uint32_t)((kc & 1) * STG_B);
        const uint32_t sB = sA + (uint32_t)A_STG_B;

        #pragma unroll
        for (int ks = 0; ks < 4; ++ks) {
            uint32_t af[4][4], bf[8][2];
            #pragma unroll
            for (int mt = 0; mt < 4; ++mt)
                ldsm_x4(af[mt][0], af[mt][1], af[mt][2], af[mt][3],
                        sA + offA + (uint32_t)(mt * 16 * GP + ks * 32));
            #pragma unroll
            for (int ntp = 0; ntp < 4; ++ntp) {
                uint32_t t0, t1, t2, t3;
                ldsm_x4(t0, t1, t2, t3, sB + offB + (uint32_t)(ntp * 16 * GP + ks * 32));
                bf[2 * ntp][0] = t0; bf[2 * ntp][1] = t1;
                bf[2 * ntp + 1][0] = t2; bf[2 * ntp + 1][1] = t3;
            }
            #pragma unroll
            for (int mt = 0; mt < 4; ++mt)
                #pragma unroll
                for (int nt = 0; nt < 8; ++nt)
                    mma_f16_16n8k16(acc[mt][nt], af[mt], bf[nt]);
        }

        __syncthreads();
        if (kc + 2 < KCHUNKS) produce(kc + 2);
    }

    #pragma unroll
    for (int mt = 0; mt < 4; ++mt) {
        #pragma unroll
        for (int half = 0; half < 2; ++half) {
            const int m = m0 + warp_m * 64 + mt * 16 + grp + half * 8;
            #pragma unroll
            for (int nt = 0; nt < 8; ++nt) {
                const int n = n0 + warp_n * 64 + nt * 8 + qd * 2;
                float vx = acc[mt][nt][half * 2 + 0] + bias[n];
                float vy = acc[mt][nt][half * 2 + 1] + bias[n + 1];
                if (MODE == 0) {
                    const int b = m >> 11;
                    const int s = m & 2047;
                    const int h = n >> 6;
                    const int a = n & 63;
                    if (z == 0) {
                        vx *= 0.125f; vy *= 0.125f;
                        *(uint32_t*)&g_qh[(((size_t)b * Hn + h) * Sn + s) * An + a] = pack_h2(vx, vy);
                    } else if (z == 1) {
                        *(uint32_t*)&g_kh[(((size_t)b * Hn + h) * Sn + s) * An + a] = pack_h2(vx, vy);
                    } else {
                        __half* Vd = g_vh + (((size_t)b * Hn + h) * An) * Sn;
                        Vd[(size_t)a * Sn + s] = __float2half_rn(vx);
                        Vd[(size_t)(a + 1) * Sn + s] = __float2half_rn(vy);
                    }
                } else {
                    float2 v2 = {vx, vy};
                    *(float2*)&outp[(size_t)m * Dn + n] = v2;
                }
            }
        }
    }
}

// ---------------------------------------------------------------------------
// Causal flash attention: P kept in registers (C-fragment == A-fragment),
// no P SMEM round-trip. SMEM = 2 KV stages only (36 KB).
// ---------------------------------------------------------------------------
constexpr int K_STG_B = 64 * 144;       // 9216
constexpr int KV_STG_B = 2 * K_STG_B;   // 18432
constexpr int FLASH_SMEM_BYTES = 2 * KV_STG_B;   // 36864

__global__ __launch_bounds__(256) void flash_mma_kernel()
{
    extern __shared__ uint32_t sm_u[];

    const int tid = threadIdx.x;
    const int lane = tid & 31;
    const int wid = tid >> 5;
    const int grp = lane >> 2;
    const int qd = lane & 3;

    const int bh = blockIdx.y;
    const size_t base = (size_t)bh * Sn * An;
    const int q0 = blockIdx.x * 128;
    const uint32_t smem_base = smem_u32(sm_u);

    const uint32_t offQ = (uint32_t)(wid * 16 + (lane & 15)) * 144 + (uint32_t)(lane >> 4) * 16;
    const uint32_t offKV = (uint32_t)(((lane >> 4) & 1) * 8 + (lane & 7)) * 144
                         + (uint32_t)((lane >> 3) & 1) * 16;

    auto produce = [&](int t) {
        const uint32_t sK = smem_base + (uint32_t)((t & 1) * KV_STG_B);
        const uint32_t sV = sK + (uint32_t)K_STG_B;
        const int j0 = t * 64;
        #pragma unroll
        for (int i = 0; i < 2; ++i) {
            int idx = i * 256 + tid;
            int r = idx >> 3;
            int seg = idx & 7;
            cp_async16(sK + (uint32_t)(r * 144 + seg * 16),
                       g_kh + base + (size_t)(j0 + r) * An + seg * 8);
        }
        #pragma unroll
        for (int i = 0; i < 2; ++i) {
            int idx = i * 256 + tid;
            int a = idx >> 3;
            int seg = idx & 7;
            cp_async16(sV + (uint32_t)(a * 144 + seg * 16),
                       g_vh + base + (size_t)a * Sn + j0 + seg * 8);
        }
        cp_commit();
    };

    produce(0);

    // Q fill via cp.async into stage-1 alias
    {
        const uint32_t sQb = smem_base + (uint32_t)KV_STG_B;
        #pragma unroll
        for (int i = 0; i < 4; ++i) {
            int idx = i * 256 + tid;
            int r = idx >> 3;
            int seg = idx & 7;
            cp_async16(sQb + (uint32_t)(r * 144 + seg * 16),
                       g_qh + base + (size_t)(q0 + r) * An + seg * 8);
        }
        cp_commit();
    }
    cp_wait<0>();
    __syncthreads();

    uint32_t qf[4][4];
    #pragma unroll
    for (int ks = 0; ks < 4; ++ks)
        ldsm_x4(qf[ks][0], qf[ks][1], qf[ks][2], qf[ks][3],
                smem_base + KV_STG_B + offQ + ks * 32);
    __syncthreads();
    produce(1);

    const int r0 = wid * 16 + grp;
    float m0r = -1e30f, m1r = -1e30f, l0r = 0.0f, l1r = 0.0f;
    float o[8][4];
    #pragma unroll
    for (int nt = 0; nt < 8; ++nt)
        #pragma unroll
        for (int e = 0; e < 4; ++e) o[nt][e] = 0.0f;

    const int grow0 = q0 + r0;
    const int grow1 = grow0 + 8;
    const int ntiles = (q0 + 128) / 64;

    for (int t = 0; t < ntiles; ++t) {
        cp_wait<1>();
        __syncthreads();

        const uint32_t sK_b = smem_base + (uint32_t)((t & 1) * KV_STG_B);
        const uint32_t sV_b = sK_b + (uint32_t)K_STG_B;
        const int j0 = t * 64;

        float sacc[8][4];
        #pragma unroll
        for (int nt = 0; nt < 8; ++nt)
            #pragma unroll
            for (int e = 0; e < 4; ++e) sacc[nt][e] = 0.0f;

        #pragma unroll
        for (int ks = 0; ks < 4; ++ks) {
            uint32_t kf[8][2];
            #pragma unroll
            for (int ntp = 0; ntp < 4; ++ntp) {
                uint32_t t0, t1, t2, t3;
                ldsm_x4(t0, t1, t2, t3, sK_b + offKV + (uint32_t)(ntp * 16 * 144 + ks * 32));
                kf[2 * ntp][0] = t0; kf[2 * ntp][1] = t1;
                kf[2 * ntp + 1][0] = t2; kf[2 * ntp + 1][1] = t3;
            }
            #pragma unroll
            for (int nt = 0; nt < 8; ++nt)
                mma_f16_16n8k16(sacc[nt], qf[ks], kf[nt]);
        }

        if (j0 + 63 > q0) {
            #pragma unroll
            for (int nt = 0; nt < 8; ++nt) {
                int c = j0 + nt * 8 + qd * 2;
                if (c > grow0)     sacc[nt][0] = -1e30f;
                if (c + 1 > grow0) sacc[nt][1] = -1e30f;
                if (c > grow1)     sacc[nt][2] = -1e30f;
                if (c + 1 > grow1) sacc[nt][3] = -1e30f;
            }
        }

        float rm0 = -1e30f, rm1 = -1e30f;
        #pragma unroll
        for (int nt = 0; nt < 8; ++nt) {
            rm0 = fmaxf(rm0, fmaxf(sacc[nt][0], sacc[nt][1]));
            rm1 = fmaxf(rm1, fmaxf(sacc[nt][2], sacc[nt][3]));
        }
        rm0 = fmaxf(rm0, __shfl_xor_sync(0xffffffffu, rm0, 1));
        rm0 = fmaxf(rm0, __shfl_xor_sync(0xffffffffu, rm0, 2));
        rm1 = fmaxf(rm1, __shfl_xor_sync(0xffffffffu, rm1, 1));
        rm1 = fmaxf(rm1, __shfl_xor_sync(0xffffffffu, rm1, 2));

        float mn0 = fmaxf(m0r, rm0);
        float mn1 = fmaxf(m1r, rm1);
        float corr0 = __expf(m0r - mn0);
        float corr1 = __expf(m1r - mn1);
        m0r = mn0; m1r = mn1;

        // softmax -> P directly as mma A-fragments in registers
        uint32_t pf[4][4];
        float rs0 = 0.0f, rs1 = 0.0f;
        #pragma unroll
        for (int nt = 0; nt < 8; ++nt) {
            float p0 = __expf(sacc[nt][0] - mn0);
            float p1 = __expf(sacc[nt][1] - mn0);
            float p2 = __expf(sacc[nt][2] - mn1);
            float p3 = __expf(sacc[nt][3] - mn1);
            rs0 += p0 + p1;
            rs1 += p2 + p3;
            pf[nt >> 1][(nt & 1) * 2 + 0] = pack_h2(p0, p1);
            pf[nt >> 1][(nt & 1) * 2 + 1] = pack_h2(p2, p3);
        }
        rs0 += __shfl_xor_sync(0xffffffffu, rs0, 1);
        rs0 += __shfl_xor_sync(0xffffffffu, rs0, 2);
        rs1 += __shfl_xor_sync(0xffffffffu, rs1, 1);
        rs1 += __shfl_xor_sync(0xffffffffu, rs1, 2);
        l0r = l0r * corr0 + rs0;
        l1r = l1r * corr1 + rs1;

        #pragma unroll
        for (int nt = 0; nt < 8; ++nt) {
            o[nt][0] *= corr0;
            o[nt][1] *= corr0;
            o[nt][2] *= corr1;
            o[nt][3] *= corr1;
        }

        // O += P @ V  (A from registers; V via ldmatrix)
        #pragma unroll
        for (int ks = 0; ks < 4; ++ks) {
            uint32_t vf[8][2];
            #pragma unroll
            for (int ntp = 0; ntp < 4; ++ntp) {
                uint32_t t0, t1, t2, t3;
                ldsm_x4(t0, t1, t2, t3, sV_b + offKV + (uint32_t)(ntp * 16 * 144 + ks * 32));
                vf[2 * ntp][0] = t0; vf[2 * ntp][1] = t1;
                vf[2 * ntp + 1][0] = t2; vf[2 * ntp + 1][1] = t3;
            }
            #pragma unroll
            for (int nt = 0; nt < 8; ++nt)
                mma_f16_16n8k16(o[nt], pf[ks], vf[nt]);
        }

        __syncthreads();
        if (t + 2 < ntiles) produce(t + 2);
    }

    const int b = bh >> 4;
    const int h = bh & 15;
    const float inv0 = 1.0f / l0r;
    const float inv1 = 1.0f / l1r;
    #pragma unroll
    for (int nt = 0; nt < 8; ++nt) {
        const int a = nt * 8 + qd * 2;
        *(uint32_t*)&g_zh[(((size_t)b * Sn + grow0) * Hn + h) * An + a] =
            pack_h2(o[nt][0] * inv0, o[nt][1] * inv0);
        *(uint32_t*)&g_zh[(((size_t)b * Sn + grow1) * Hn + h) * An + a] =
            pack_h2(o[nt][2] * inv1, o[nt][3] * inv1);
    }
}

// ---------------------------------------------------------------------------
extern "C" void kernel_launch(void* const* d_in, const int* in_sizes, int n_in,
                              void* d_out, int out_size)
{
    const float* residual = (const float*)d_in[0];
    const float* Wq = (const float*)d_in[1];
    const float* Wk = (const float*)d_in[2];
    const float* Wv = (const float*)d_in[3];
    const float* Wo = (const float*)d_in[4];
    const float* bq = (const float*)d_in[5];
    const float* bk = (const float*)d_in[6];
    const float* bv = (const float*)d_in[7];
    const float* bo = (const float*)d_in[8];
    float* out = (float*)d_out;

    cudaFuncSetAttribute(flash_mma_kernel, cudaFuncAttributeMaxDynamicSharedMemorySize,
                         FLASH_SMEM_BYTES);
    cudaFuncSetAttribute(gemm_mma_kernel<0>, cudaFuncAttributeMaxDynamicSharedMemorySize,
                         GEMM_SMEM);
    cudaFuncSetAttribute(gemm_mma_kernel<1>, cudaFuncAttributeMaxDynamicSharedMemorySize,
                         GEMM_SMEM);

    // 0) fp16 prepass
    conv_resid_kernel<<<1024, 256>>>(residual);
    transpose_qkv_kernel<<<dim3(1024 / 32, 64 / 32, 48), dim3(32, 8)>>>(Wq, Wk, Wv);
    transpose_wo_kernel<<<dim3(32, 32), dim3(32, 8)>>>(Wo);

    // 1) QKV projections
    gemm_mma_kernel<0><<<dim3(HA / 128, Mrows / 128, 3), 128, GEMM_SMEM>>>(
        bq, bk, bv, nullptr);

    // 2) Causal flash attention (P in registers)
    flash_mma_kernel<<<dim3(Sn / 128, Bn * Hn), 256, FLASH_SMEM_BYTES>>>();

    // 3) Output projection
    gemm_mma_kernel<1><<<dim3(Dn / 128, Mrows / 128, 1), 128, GEMM_SMEM>>>(
        bo, nullptr, nullptr, out);
}